// round 1
// baseline (speedup 1.0000x reference)
#include <cuda_runtime.h>
#include <cuda_bf16.h>
#include <math.h>

// Problem constants
#define B_SZ   4
#define L_SEQ  2048
#define C_DIM  1024
#define H_NUM  16
#define DH     64
#define M_ROWS (B_SZ * L_SEQ)          // 8192
#define N_QKV  (3 * C_DIM)             // 3072

// ---------------------------------------------------------------------------
// Static device scratch (allocation-free rule: __device__ globals)
// ---------------------------------------------------------------------------
__device__ float g_qkv[M_ROWS * N_QKV];          // (B*L, 3C)   ~100.7 MB
__device__ float g_q[B_SZ * H_NUM * L_SEQ * DH]; // (B,H,L,Dh)  ~33.6 MB
__device__ float g_k[B_SZ * H_NUM * L_SEQ * DH];
__device__ float g_v[B_SZ * H_NUM * L_SEQ * DH];
__device__ float g_y[M_ROWS * C_DIM];            // (B*L, C)    ~33.6 MB

// ---------------------------------------------------------------------------
// Generic tiled fp32 GEMM + bias: C[M,N] = A[M,K] @ B[K,N] + bias[N]
// BM=BN=64, BK=16, 256 threads, 4x4 microtile per thread.
// ---------------------------------------------------------------------------
__device__ __forceinline__ void gemm_body(const float* __restrict__ A,
                                          const float* __restrict__ Bm,
                                          const float* __restrict__ bias,
                                          float* __restrict__ C,
                                          int N, int K) {
    const int BM = 64, BN = 64, BK = 16, TM = 4, TN = 4;
    __shared__ float As[BK][BM];   // [k][m]
    __shared__ float Bs[BK][BN];   // [k][n]

    const int tx = threadIdx.x & 15;        // 0..15  (N direction)
    const int ty = threadIdx.x >> 4;        // 0..15  (M direction)
    const int rowBlock = blockIdx.y * BM;
    const int colBlock = blockIdx.x * BN;
    const int row0 = rowBlock + ty * TM;
    const int col0 = colBlock + tx * TN;

    float acc[TM][TN];
#pragma unroll
    for (int i = 0; i < TM; i++)
#pragma unroll
        for (int j = 0; j < TN; j++) acc[i][j] = 0.f;

    for (int k0 = 0; k0 < K; k0 += BK) {
        // Load A tile (BM x BK = 1024 elems), 4 per thread
#pragma unroll
        for (int i = threadIdx.x; i < BM * BK; i += 256) {
            int r = i >> 4;          // m
            int c = i & 15;          // k
            As[c][r] = A[(rowBlock + r) * K + k0 + c];
        }
        // Load B tile (BK x BN = 1024 elems), coalesced on N
#pragma unroll
        for (int i = threadIdx.x; i < BK * BN; i += 256) {
            int r = i >> 6;          // k
            int c = i & 63;          // n
            Bs[r][c] = Bm[(k0 + r) * N + colBlock + c];
        }
        __syncthreads();

#pragma unroll
        for (int kk = 0; kk < BK; kk++) {
            float4 av = *reinterpret_cast<const float4*>(&As[kk][ty * TM]);
            float4 bv = *reinterpret_cast<const float4*>(&Bs[kk][tx * TN]);
            float a[TM] = {av.x, av.y, av.z, av.w};
            float b[TN] = {bv.x, bv.y, bv.z, bv.w};
#pragma unroll
            for (int i = 0; i < TM; i++)
#pragma unroll
                for (int j = 0; j < TN; j++)
                    acc[i][j] = fmaf(a[i], b[j], acc[i][j]);
        }
        __syncthreads();
    }

#pragma unroll
    for (int i = 0; i < TM; i++) {
#pragma unroll
        for (int j = 0; j < TN; j++) {
            C[(row0 + i) * N + col0 + j] = acc[i][j] + bias[col0 + j];
        }
    }
}

__global__ __launch_bounds__(256)
void qkv_gemm_kernel(const float* __restrict__ x,
                     const float* __restrict__ W,
                     const float* __restrict__ b) {
    gemm_body(x, W, b, g_qkv, N_QKV, C_DIM);
}

__global__ __launch_bounds__(256)
void out_gemm_kernel(const float* __restrict__ W,
                     const float* __restrict__ b,
                     float* __restrict__ out) {
    gemm_body(g_y, W, b, out, C_DIM, C_DIM);
}

// ---------------------------------------------------------------------------
// RoPE + split: g_qkv (B*L, 3C) -> g_q/g_k (rotated), g_v in (B,H,L,Dh)
// ---------------------------------------------------------------------------
__global__ __launch_bounds__(256)
void rope_split_kernel() {
    int idx = blockIdx.x * blockDim.x + threadIdx.x;
    const int total = B_SZ * H_NUM * L_SEQ * DH;   // 8,388,608
    if (idx >= total) return;

    int d  = idx & 63;
    int l  = (idx >> 6) & (L_SEQ - 1);
    int bh = idx >> 17;            // 0..63  (b*16 + h)
    int h  = bh & 15;
    int b  = bh >> 4;

    int row  = b * L_SEQ + l;
    int base = row * N_QKV + h * DH;

    float qv = g_qkv[base + d];
    float kv = g_qkv[base + C_DIM + d];
    float vv = g_qkv[base + 2 * C_DIM + d];

    int fi = d & 31;
    // inv_freq = 10000^(-fi/32): compute in double to kill accumulation error
    double invd = exp((double)fi * -0.28782313662425565);  // -ln(10000)/32
    float ang = (float)((double)l * invd);
    float sn, cs;
    sincosf(ang, &sn, &cs);

    int d2 = (d < 32) ? d + 32 : d - 32;
    float qrot = (d < 32) ? -g_qkv[base + d2] : g_qkv[base + d2];
    float krot = (d < 32) ? -g_qkv[base + C_DIM + d2] : g_qkv[base + C_DIM + d2];

    g_q[idx] = fmaf(qv, cs, qrot * sn);
    g_k[idx] = fmaf(kv, cs, krot * sn);
    g_v[idx] = vv;
}

// ---------------------------------------------------------------------------
// Flash attention (fp32, causal, online softmax).
// Grid: (L/64, H, B). 64 threads/block, one query row per thread.
// q row and output accumulator live in registers; K/V tiles (32x64) in SMEM,
// read via warp-broadcast (all lanes same address).
// ---------------------------------------------------------------------------
__global__ __launch_bounds__(64)
void flash_attn_kernel(const unsigned char* __restrict__ pad) {
    const int Bc = 32;
    const int qt  = blockIdx.x;
    const int h   = blockIdx.y;
    const int b   = blockIdx.z;
    const int tid = threadIdx.x;           // 0..63
    const int qi  = qt * 64 + tid;         // global query row

    const int bh = b * H_NUM + h;
    const float* qbase = g_q + (size_t)bh * L_SEQ * DH;
    const float* kbase = g_k + (size_t)bh * L_SEQ * DH;
    const float* vbase = g_v + (size_t)bh * L_SEQ * DH;

    __shared__ float Ksh[Bc][DH];
    __shared__ float Vsh[Bc][DH];

    float qreg[DH];
#pragma unroll
    for (int d = 0; d < DH; d++)
        qreg[d] = qbase[qi * DH + d] * 0.125f;   // 1/sqrt(64)

    float acc[DH];
#pragma unroll
    for (int d = 0; d < DH; d++) acc[d] = 0.f;
    float m = -INFINITY, lsum = 0.f;

    const int nkt = 2 * qt + 2;             // key tiles covering [0, 64*qt+64)
    for (int kt = 0; kt < nkt; kt++) {
        int k0 = kt * Bc;
        // Cooperative load of K/V tiles (coalesced)
#pragma unroll
        for (int n = 0; n < (Bc * DH) / 64; n++) {
            Ksh[n][tid] = kbase[(k0 + n) * DH + tid];
            Vsh[n][tid] = vbase[(k0 + n) * DH + tid];
        }
        __syncthreads();

        float s[Bc];
        float mt = -INFINITY;
#pragma unroll
        for (int j = 0; j < Bc; j++) {
            float sum = 0.f;
#pragma unroll
            for (int d = 0; d < DH; d++)
                sum = fmaf(qreg[d], Ksh[j][d], sum);
            int kj = k0 + j;
            bool ok = (kj <= qi) && (pad[b * L_SEQ + kj] == 0);
            s[j] = ok ? sum : -INFINITY;
            mt = fmaxf(mt, s[j]);
        }

        float mnew = fmaxf(m, mt);
        if (mnew != -INFINITY) {
            float corr = (m == -INFINITY) ? 0.f : __expf(m - mnew);
            lsum *= corr;
#pragma unroll
            for (int d = 0; d < DH; d++) acc[d] *= corr;
#pragma unroll
            for (int j = 0; j < Bc; j++) {
                float p = __expf(s[j] - mnew);
                lsum += p;
#pragma unroll
                for (int d = 0; d < DH; d++)
                    acc[d] = fmaf(p, Vsh[j][d], acc[d]);
            }
            m = mnew;
        }
        __syncthreads();
    }

    float inv = 1.f / lsum;
    float* yrow = g_y + ((size_t)b * L_SEQ + qi) * C_DIM + h * DH;
#pragma unroll
    for (int d = 0; d < DH; d++)
        yrow[d] = acc[d] * inv;
}

// ---------------------------------------------------------------------------
// Launch
// ---------------------------------------------------------------------------
extern "C" void kernel_launch(void* const* d_in, const int* in_sizes, int n_in,
                              void* d_out, int out_size) {
    const float*         x    = (const float*)d_in[0];
    const unsigned char* pad  = (const unsigned char*)d_in[1];
    const float*         Wqkv = (const float*)d_in[2];
    const float*         bqkv = (const float*)d_in[3];
    const float*         Wout = (const float*)d_in[4];
    const float*         bout = (const float*)d_in[5];
    float*               out  = (float*)d_out;

    // 1) QKV projection
    dim3 g1(N_QKV / 64, M_ROWS / 64);
    qkv_gemm_kernel<<<g1, 256>>>(x, Wqkv, bqkv);

    // 2) RoPE + split into (B,H,L,Dh)
    int total = B_SZ * H_NUM * L_SEQ * DH;
    rope_split_kernel<<<(total + 255) / 256, 256>>>();

    // 3) Causal flash attention
    dim3 ga(L_SEQ / 64, H_NUM, B_SZ);
    flash_attn_kernel<<<ga, 64>>>(pad);

    // 4) Output projection
    dim3 g2(C_DIM / 64, M_ROWS / 64);
    out_gemm_kernel<<<g2, 256>>>(Wout, bout, out);
}

// round 2
// speedup vs baseline: 2.2056x; 2.2056x over previous
#include <cuda_runtime.h>
#include <cuda_bf16.h>
#include <math.h>

// Problem constants
#define B_SZ   4
#define L_SEQ  2048
#define C_DIM  1024
#define H_NUM  16
#define DH     64
#define M_ROWS (B_SZ * L_SEQ)          // 8192
#define N_QKV  (3 * C_DIM)             // 3072
#define BH_NUM (B_SZ * H_NUM)          // 64

// ---------------------------------------------------------------------------
// Static device scratch
// ---------------------------------------------------------------------------
__device__ float g_qkv[M_ROWS * N_QKV];              // (B*L, 3C)
__device__ float g_qT[BH_NUM * DH * L_SEQ];          // (bh, d, L)  transposed
__device__ float g_kT[BH_NUM * DH * L_SEQ];          // (bh, d, L)  transposed
__device__ float g_y[M_ROWS * C_DIM];                // (B*L, C)

// ---------------------------------------------------------------------------
// 128x128x16 fp32 GEMM + bias. 256 threads, 8x8 microtile.
// C[M,N] = A[M,K] @ B[K,N] + bias[N]
// ---------------------------------------------------------------------------
__device__ __forceinline__ void gemm128_body(const float* __restrict__ A,
                                             const float* __restrict__ Bm,
                                             const float* __restrict__ bias,
                                             float* __restrict__ C,
                                             int N, int K) {
    __shared__ float As[16][132];   // [k][m], pad 4
    __shared__ float Bs[16][128];   // [k][n]

    const int tid = threadIdx.x;
    const int tx = tid & 15;                // N dir
    const int ty = tid >> 4;                // M dir
    const int rowBlock = blockIdx.y * 128;
    const int colBlock = blockIdx.x * 128;

    // A-load mapping: each thread loads 2 float4 (one 32B chunk) of one row slice
    const int ar = tid >> 1;                // 0..127 (row within tile)
    const int ak = (tid & 1) * 8;           // 0 or 8 (k offset)
    // B-load mapping: 2 passes of (kr, nc)
    const float* Arow = A + (size_t)(rowBlock + ar) * K + ak;

    float acc[8][8];
#pragma unroll
    for (int i = 0; i < 8; i++)
#pragma unroll
        for (int j = 0; j < 8; j++) acc[i][j] = 0.f;

    for (int k0 = 0; k0 < K; k0 += 16) {
        // ---- load A tile (128x16) ----
        float4 a0 = *reinterpret_cast<const float4*>(Arow + k0);
        float4 a1 = *reinterpret_cast<const float4*>(Arow + k0 + 4);
        As[ak + 0][ar] = a0.x;  As[ak + 1][ar] = a0.y;
        As[ak + 2][ar] = a0.z;  As[ak + 3][ar] = a0.w;
        As[ak + 4][ar] = a1.x;  As[ak + 5][ar] = a1.y;
        As[ak + 6][ar] = a1.z;  As[ak + 7][ar] = a1.w;
        // ---- load B tile (16x128) ----
#pragma unroll
        for (int p = 0; p < 2; p++) {
            int idx = p * 256 + tid;
            int kr = idx >> 5;              // 0..15
            int nc = (idx & 31) * 4;        // 0..124
            *reinterpret_cast<float4*>(&Bs[kr][nc]) =
                *reinterpret_cast<const float4*>(Bm + (size_t)(k0 + kr) * N + colBlock + nc);
        }
        __syncthreads();

#pragma unroll
        for (int kk = 0; kk < 16; kk++) {
            float4 av0 = *reinterpret_cast<const float4*>(&As[kk][ty * 8]);
            float4 av1 = *reinterpret_cast<const float4*>(&As[kk][ty * 8 + 4]);
            float4 bv0 = *reinterpret_cast<const float4*>(&Bs[kk][tx * 8]);
            float4 bv1 = *reinterpret_cast<const float4*>(&Bs[kk][tx * 8 + 4]);
            float a[8] = {av0.x, av0.y, av0.z, av0.w, av1.x, av1.y, av1.z, av1.w};
            float b[8] = {bv0.x, bv0.y, bv0.z, bv0.w, bv1.x, bv1.y, bv1.z, bv1.w};
#pragma unroll
            for (int i = 0; i < 8; i++)
#pragma unroll
                for (int j = 0; j < 8; j++)
                    acc[i][j] = fmaf(a[i], b[j], acc[i][j]);
        }
        __syncthreads();
    }

    const int col0 = colBlock + tx * 8;
    float4 bias0 = *reinterpret_cast<const float4*>(bias + col0);
    float4 bias1 = *reinterpret_cast<const float4*>(bias + col0 + 4);
#pragma unroll
    for (int i = 0; i < 8; i++) {
        int row = rowBlock + ty * 8 + i;
        float4 c0 = make_float4(acc[i][0] + bias0.x, acc[i][1] + bias0.y,
                                acc[i][2] + bias0.z, acc[i][3] + bias0.w);
        float4 c1 = make_float4(acc[i][4] + bias1.x, acc[i][5] + bias1.y,
                                acc[i][6] + bias1.z, acc[i][7] + bias1.w);
        *reinterpret_cast<float4*>(C + (size_t)row * N + col0)     = c0;
        *reinterpret_cast<float4*>(C + (size_t)row * N + col0 + 4) = c1;
    }
}

__global__ __launch_bounds__(256)
void qkv_gemm_kernel(const float* __restrict__ x,
                     const float* __restrict__ W,
                     const float* __restrict__ b) {
    gemm128_body(x, W, b, g_qkv, N_QKV, C_DIM);
}

__global__ __launch_bounds__(256)
void out_gemm_kernel(const float* __restrict__ W,
                     const float* __restrict__ b,
                     float* __restrict__ out) {
    gemm128_body(g_y, W, b, out, C_DIM, C_DIM);
}

// ---------------------------------------------------------------------------
// RoPE + transpose: g_qkv -> g_qT/g_kT in (bh, d, L) layout.
// Block: 64 L x 64 d tile of one head. Coalesced read, smem transpose,
// coalesced write.
// ---------------------------------------------------------------------------
__global__ __launch_bounds__(256)
void rope_transpose_kernel() {
    __shared__ float Tq[DH][65];
    __shared__ float Tk[DH][65];

    const int tid = threadIdx.x;
    const int l0 = blockIdx.x * 64;
    const int bh = blockIdx.y;
    const int b  = bh >> 4;
    const int h  = bh & 15;

    // read + rope (coalesced over d)
#pragma unroll
    for (int p = 0; p < 16; p++) {
        int e = p * 256 + tid;
        int l = e >> 6;            // 0..63 local
        int d = e & 63;
        int row  = b * L_SEQ + l0 + l;
        int base = row * N_QKV + h * DH;

        float qv = g_qkv[base + d];
        float kv = g_qkv[base + C_DIM + d];
        int d2 = (d < 32) ? d + 32 : d - 32;
        float qr = (d < 32) ? -g_qkv[base + d2] : g_qkv[base + d2];
        float kr = (d < 32) ? -g_qkv[base + C_DIM + d2] : g_qkv[base + C_DIM + d2];

        int fi = d & 31;
        double invd = exp((double)fi * -0.28782313662425565);  // -ln(10000)/32
        float ang = (float)((double)(l0 + l) * invd);
        float sn, cs;
        sincosf(ang, &sn, &cs);

        Tq[d][l] = fmaf(qv, cs, qr * sn);
        Tk[d][l] = fmaf(kv, cs, kr * sn);
    }
    __syncthreads();

    // write (coalesced over l)
    float* qout = g_qT + (size_t)bh * DH * L_SEQ;
    float* kout = g_kT + (size_t)bh * DH * L_SEQ;
#pragma unroll
    for (int p = 0; p < 16; p++) {
        int e = p * 256 + tid;
        int d = e >> 6;
        int l = e & 63;
        qout[d * L_SEQ + l0 + l] = Tq[d][l];
        kout[d * L_SEQ + l0 + l] = Tk[d][l];
    }
}

// ---------------------------------------------------------------------------
// Flash attention, 2-stage tiled. 64 q x 64 k tiles, 256 threads (16x16),
// each thread a 4x4 score microtile and a 4(q)x4(d) output microtile.
// P tile staged through SMEM aliased over the K tile. 48KB static SMEM.
// ---------------------------------------------------------------------------
__global__ __launch_bounds__(256)
void flash_attn_kernel(const unsigned char* __restrict__ pad) {
    __shared__ float Qs[DH * 64];    // [d][q]   16KB
    __shared__ float KP[DH * 64];    // Ks [d][k] then Ps [q][j]   16KB
    __shared__ float Vs[64 * DH];    // [j][d]   16KB

    const int tid = threadIdx.x;
    const int tx = tid & 15;             // key / dim direction
    const int ty = tid >> 4;             // query direction
    const int i0 = ty * 4;               // local query base
    const int j0 = tx * 4;               // local key base (and dim base d0)

    const int qt = blockIdx.x;
    const int bh = blockIdx.y;
    const int b  = bh >> 4;
    const int h  = bh & 15;
    const int q0 = qt * 64;

    const float* qTb = g_qT + (size_t)bh * DH * L_SEQ;
    const float* kTb = g_kT + (size_t)bh * DH * L_SEQ;

    // Load Q tile: Qs[d][q] (pre-scaled by 1/sqrt(Dh))
#pragma unroll
    for (int p = 0; p < 16; p++) {
        int e = p * 256 + tid;
        int d = e >> 6;
        int q = e & 63;
        Qs[d * 64 + q] = qTb[d * L_SEQ + q0 + q] * 0.125f;
    }

    float o[4][4];
#pragma unroll
    for (int i = 0; i < 4; i++)
#pragma unroll
        for (int j = 0; j < 4; j++) o[i][j] = 0.f;
    float m_i[4] = {-INFINITY, -INFINITY, -INFINITY, -INFINITY};
    float l_i[4] = {0.f, 0.f, 0.f, 0.f};

    for (int kt = 0; kt <= qt; kt++) {
        const int k0 = kt * 64;
        // ---- load K tile (direct, transposed layout) and V tile ----
        __syncthreads();     // previous iter's Ps/Vs reads done
#pragma unroll
        for (int p = 0; p < 16; p++) {
            int e = p * 256 + tid;
            int d = e >> 6;
            int k = e & 63;
            KP[d * 64 + k] = kTb[d * L_SEQ + k0 + k];
        }
#pragma unroll
        for (int p = 0; p < 4; p++) {
            int idx = p * 256 + tid;
            int j  = idx >> 4;
            int dq = (idx & 15) * 4;
            *reinterpret_cast<float4*>(&Vs[j * DH + dq]) =
                *reinterpret_cast<const float4*>(
                    g_qkv + (size_t)(b * L_SEQ + k0 + j) * N_QKV + 2 * C_DIM + h * DH + dq);
        }
        __syncthreads();

        // ---- S = Q K^T ----
        float s[4][4];
#pragma unroll
        for (int i = 0; i < 4; i++)
#pragma unroll
            for (int j = 0; j < 4; j++) s[i][j] = 0.f;
#pragma unroll 8
        for (int d = 0; d < DH; d++) {
            float4 q4 = *reinterpret_cast<const float4*>(&Qs[d * 64 + i0]);
            float4 k4 = *reinterpret_cast<const float4*>(&KP[d * 64 + j0]);
            float qa[4] = {q4.x, q4.y, q4.z, q4.w};
            float ka[4] = {k4.x, k4.y, k4.z, k4.w};
#pragma unroll
            for (int i = 0; i < 4; i++)
#pragma unroll
                for (int j = 0; j < 4; j++)
                    s[i][j] = fmaf(qa[i], ka[j], s[i][j]);
        }

        // ---- masks ----
        uchar4 pb = *reinterpret_cast<const uchar4*>(pad + b * L_SEQ + k0 + j0);
        unsigned char pv[4] = {pb.x, pb.y, pb.z, pb.w};
        if (kt == qt) {
#pragma unroll
            for (int i = 0; i < 4; i++)
#pragma unroll
                for (int j = 0; j < 4; j++)
                    if ((j0 + j > i0 + i) || pv[j]) s[i][j] = -INFINITY;
        } else {
#pragma unroll
            for (int i = 0; i < 4; i++)
#pragma unroll
                for (int j = 0; j < 4; j++)
                    if (pv[j]) s[i][j] = -INFINITY;
        }

        // ---- online softmax (row reductions across 16 tx lanes) ----
        float corr[4];
#pragma unroll
        for (int i = 0; i < 4; i++) {
            float mt = fmaxf(fmaxf(s[i][0], s[i][1]), fmaxf(s[i][2], s[i][3]));
#pragma unroll
            for (int off = 8; off >= 1; off >>= 1)
                mt = fmaxf(mt, __shfl_xor_sync(0xffffffffu, mt, off, 16));
            float mnew = fmaxf(m_i[i], mt);
            corr[i] = __expf(m_i[i] - mnew);          // 0 when m_i = -inf
            m_i[i] = mnew;
            float rs = 0.f;
#pragma unroll
            for (int j = 0; j < 4; j++) {
                float p = __expf(s[i][j] - mnew);
                s[i][j] = p;                          // s now holds P
                rs += p;
            }
#pragma unroll
            for (int off = 8; off >= 1; off >>= 1)
                rs += __shfl_xor_sync(0xffffffffu, rs, off, 16);
            l_i[i] = l_i[i] * corr[i] + rs;
#pragma unroll
            for (int j = 0; j < 4; j++) o[i][j] *= corr[i];
        }

        // ---- stage P through SMEM (aliases K tile) ----
        __syncthreads();      // everyone done reading Ks
#pragma unroll
        for (int i = 0; i < 4; i++) {
            float4 p4 = make_float4(s[i][0], s[i][1], s[i][2], s[i][3]);
            *reinterpret_cast<float4*>(&KP[(i0 + i) * 64 + j0]) = p4;   // Ps[q][j]
        }
        __syncthreads();

        // ---- O += P V ----
#pragma unroll
        for (int j4 = 0; j4 < 16; j4++) {
            float4 pq[4];
#pragma unroll
            for (int i = 0; i < 4; i++)
                pq[i] = *reinterpret_cast<const float4*>(&KP[(i0 + i) * 64 + j4 * 4]);
#pragma unroll
            for (int jj = 0; jj < 4; jj++) {
                float4 v4 = *reinterpret_cast<const float4*>(&Vs[(j4 * 4 + jj) * DH + j0]);
                float pv4[4] = {((const float*)&pq[0])[jj], ((const float*)&pq[1])[jj],
                                ((const float*)&pq[2])[jj], ((const float*)&pq[3])[jj]};
#pragma unroll
                for (int i = 0; i < 4; i++) {
                    o[i][0] = fmaf(pv4[i], v4.x, o[i][0]);
                    o[i][1] = fmaf(pv4[i], v4.y, o[i][1]);
                    o[i][2] = fmaf(pv4[i], v4.z, o[i][2]);
                    o[i][3] = fmaf(pv4[i], v4.w, o[i][3]);
                }
            }
        }
    }

    // ---- epilogue ----
#pragma unroll
    for (int i = 0; i < 4; i++) {
        float inv = 1.f / l_i[i];
        float4 r = make_float4(o[i][0] * inv, o[i][1] * inv, o[i][2] * inv, o[i][3] * inv);
        int q = q0 + i0 + i;
        *reinterpret_cast<float4*>(
            g_y + (size_t)(b * L_SEQ + q) * C_DIM + h * DH + j0) = r;
    }
}

// ---------------------------------------------------------------------------
// Launch
// ---------------------------------------------------------------------------
extern "C" void kernel_launch(void* const* d_in, const int* in_sizes, int n_in,
                              void* d_out, int out_size) {
    const float*         x    = (const float*)d_in[0];
    const unsigned char* pad  = (const unsigned char*)d_in[1];
    const float*         Wqkv = (const float*)d_in[2];
    const float*         bqkv = (const float*)d_in[3];
    const float*         Wout = (const float*)d_in[4];
    const float*         bout = (const float*)d_in[5];
    float*               out  = (float*)d_out;

    dim3 g1(N_QKV / 128, M_ROWS / 128);
    qkv_gemm_kernel<<<g1, 256>>>(x, Wqkv, bqkv);

    dim3 gr(L_SEQ / 64, BH_NUM);
    rope_transpose_kernel<<<gr, 256>>>();

    dim3 ga(L_SEQ / 64, BH_NUM);
    flash_attn_kernel<<<ga, 256>>>(pad);

    dim3 g2(C_DIM / 128, M_ROWS / 128);
    out_gemm_kernel<<<g2, 256>>>(Wout, bout, out);
}

// round 3
// speedup vs baseline: 3.3580x; 1.5225x over previous
#include <cuda_runtime.h>
#include <cuda_bf16.h>
#include <math.h>

// Problem constants
#define B_SZ   4
#define L_SEQ  2048
#define C_DIM  1024
#define H_NUM  16
#define DH     64
#define M_ROWS (B_SZ * L_SEQ)          // 8192
#define N_QKV  (3 * C_DIM)             // 3072
#define BH_NUM (B_SZ * H_NUM)          // 64

// ---------------------------------------------------------------------------
// Static device scratch
// ---------------------------------------------------------------------------
__device__ float g_qkv[M_ROWS * N_QKV];              // (B*L, 3C)
__device__ float g_qT[BH_NUM * DH * L_SEQ];          // (bh, d, L)
__device__ float g_kT[BH_NUM * DH * L_SEQ];          // (bh, d, L)
__device__ float g_y[M_ROWS * C_DIM];                // (B*L, C)
__device__ float g_cs[L_SEQ][32];                    // RoPE cos table
__device__ float g_sn[L_SEQ][32];                    // RoPE sin table

// ---------------------------------------------------------------------------
// tf32 helpers
// ---------------------------------------------------------------------------
__device__ __forceinline__ unsigned f2tf(float f) {
    unsigned u;
    asm("cvt.rna.tf32.f32 %0, %1;" : "=r"(u) : "f"(f));
    return u;
}

__device__ __forceinline__ void mma_tf32(float* c, const unsigned* a, const unsigned* b) {
    asm("mma.sync.aligned.m16n8k8.row.col.f32.tf32.tf32.f32 "
        "{%0,%1,%2,%3}, {%4,%5,%6,%7}, {%8,%9}, {%0,%1,%2,%3};"
        : "+f"(c[0]), "+f"(c[1]), "+f"(c[2]), "+f"(c[3])
        : "r"(a[0]), "r"(a[1]), "r"(a[2]), "r"(a[3]), "r"(b[0]), "r"(b[1]));
}

// ---------------------------------------------------------------------------
// tf32 tensor-core GEMM + bias: C[M,N] = A[M,K] @ B[K,N] + bias[N]
// 128x128x16 block tile, 256 threads (8 warps, 2m x 4n), warp tile 64x32.
// Double-buffered SMEM, cvt.rna.tf32 on the store path.
// ---------------------------------------------------------------------------
#define AS_STRIDE 20     // 16 + 4 pad  -> LDS frag banks (20g+t) all distinct
#define BS_STRIDE 136    // 128 + 8 pad -> LDS frag banks (8t+g)  all distinct

__device__ __forceinline__ void gemm_tc_body(const float* __restrict__ A,
                                             const float* __restrict__ Bm,
                                             const float* __restrict__ bias,
                                             float* __restrict__ C,
                                             int N, int K) {
    __shared__ unsigned As[2][128 * AS_STRIDE];
    __shared__ unsigned Bs[2][16 * BS_STRIDE];

    const int tid  = threadIdx.x;
    const int lane = tid & 31;
    const int wid  = tid >> 5;
    const int warp_m = wid & 1;             // 0..1  (64 rows each)
    const int warp_n = wid >> 1;            // 0..3  (32 cols each)
    const int grp = lane >> 2;              // 0..7
    const int tig = lane & 3;               // 0..3

    const int rowBlock = blockIdx.y * 128;
    const int colBlock = blockIdx.x * 128;

    // global-load mapping
    const int ar = tid >> 1;                // 0..127
    const int ak = (tid & 1) * 8;           // 0 or 8
    const int kr = tid >> 4;                // 0..15
    const int nc = (tid & 15) * 8;          // 0..120
    const float* Arow = A + (size_t)(rowBlock + ar) * K + ak;
    const float* Bcol = Bm + (size_t)kr * N + colBlock + nc;

    float acc[4][4][4];
#pragma unroll
    for (int mt = 0; mt < 4; mt++)
#pragma unroll
        for (int nt = 0; nt < 4; nt++)
#pragma unroll
            for (int r = 0; r < 4; r++) acc[mt][nt][r] = 0.f;

    const int nk = K >> 4;

    // ---- preload tile 0 ----
    {
        float4 a0 = *reinterpret_cast<const float4*>(Arow);
        float4 a1 = *reinterpret_cast<const float4*>(Arow + 4);
        float4 b0 = *reinterpret_cast<const float4*>(Bcol);
        float4 b1 = *reinterpret_cast<const float4*>(Bcol + 4);
        uint4 ua0 = make_uint4(f2tf(a0.x), f2tf(a0.y), f2tf(a0.z), f2tf(a0.w));
        uint4 ua1 = make_uint4(f2tf(a1.x), f2tf(a1.y), f2tf(a1.z), f2tf(a1.w));
        uint4 ub0 = make_uint4(f2tf(b0.x), f2tf(b0.y), f2tf(b0.z), f2tf(b0.w));
        uint4 ub1 = make_uint4(f2tf(b1.x), f2tf(b1.y), f2tf(b1.z), f2tf(b1.w));
        *reinterpret_cast<uint4*>(&As[0][ar * AS_STRIDE + ak])     = ua0;
        *reinterpret_cast<uint4*>(&As[0][ar * AS_STRIDE + ak + 4]) = ua1;
        *reinterpret_cast<uint4*>(&Bs[0][kr * BS_STRIDE + nc])     = ub0;
        *reinterpret_cast<uint4*>(&Bs[0][kr * BS_STRIDE + nc + 4]) = ub1;
    }
    __syncthreads();

    for (int kc = 0; kc < nk; kc++) {
        const int buf = kc & 1;

        // prefetch next tile into registers
        float4 na0, na1, nb0, nb1;
        if (kc + 1 < nk) {
            const float* Ap = Arow + (size_t)(kc + 1) * 16;
            const float* Bp = Bcol + (size_t)(kc + 1) * 16 * N;
            na0 = *reinterpret_cast<const float4*>(Ap);
            na1 = *reinterpret_cast<const float4*>(Ap + 4);
            nb0 = *reinterpret_cast<const float4*>(Bp);
            nb1 = *reinterpret_cast<const float4*>(Bp + 4);
        }

        // ---- compute on current buffer ----
        const unsigned* Ab = As[buf];
        const unsigned* Bb = Bs[buf];
#pragma unroll
        for (int kk = 0; kk < 16; kk += 8) {
            unsigned af[4][4];
#pragma unroll
            for (int mt = 0; mt < 4; mt++) {
                int r0 = (warp_m * 64 + mt * 16 + grp) * AS_STRIDE + kk + tig;
                af[mt][0] = Ab[r0];
                af[mt][1] = Ab[r0 + 8 * AS_STRIDE];
                af[mt][2] = Ab[r0 + 4];
                af[mt][3] = Ab[r0 + 8 * AS_STRIDE + 4];
            }
            unsigned bf[4][2];
#pragma unroll
            for (int nt = 0; nt < 4; nt++) {
                int c0 = (kk + tig) * BS_STRIDE + warp_n * 32 + nt * 8 + grp;
                bf[nt][0] = Bb[c0];
                bf[nt][1] = Bb[c0 + 4 * BS_STRIDE];
            }
#pragma unroll
            for (int mt = 0; mt < 4; mt++)
#pragma unroll
                for (int nt = 0; nt < 4; nt++)
                    mma_tf32(acc[mt][nt], af[mt], bf[nt]);
        }

        // ---- stage next tile ----
        if (kc + 1 < nk) {
            const int nb = buf ^ 1;
            uint4 ua0 = make_uint4(f2tf(na0.x), f2tf(na0.y), f2tf(na0.z), f2tf(na0.w));
            uint4 ua1 = make_uint4(f2tf(na1.x), f2tf(na1.y), f2tf(na1.z), f2tf(na1.w));
            uint4 ub0 = make_uint4(f2tf(nb0.x), f2tf(nb0.y), f2tf(nb0.z), f2tf(nb0.w));
            uint4 ub1 = make_uint4(f2tf(nb1.x), f2tf(nb1.y), f2tf(nb1.z), f2tf(nb1.w));
            *reinterpret_cast<uint4*>(&As[nb][ar * AS_STRIDE + ak])     = ua0;
            *reinterpret_cast<uint4*>(&As[nb][ar * AS_STRIDE + ak + 4]) = ua1;
            *reinterpret_cast<uint4*>(&Bs[nb][kr * BS_STRIDE + nc])     = ub0;
            *reinterpret_cast<uint4*>(&Bs[nb][kr * BS_STRIDE + nc + 4]) = ub1;
        }
        __syncthreads();
    }

    // ---- epilogue: D frag layout rows (grp, grp+8), cols (2*tig, 2*tig+1) ----
#pragma unroll
    for (int nt = 0; nt < 4; nt++) {
        int col = colBlock + warp_n * 32 + nt * 8 + tig * 2;
        float bx = bias[col], by = bias[col + 1];
#pragma unroll
        for (int mt = 0; mt < 4; mt++) {
            int row = rowBlock + warp_m * 64 + mt * 16 + grp;
            *reinterpret_cast<float2*>(C + (size_t)row * N + col) =
                make_float2(acc[mt][nt][0] + bx, acc[mt][nt][1] + by);
            *reinterpret_cast<float2*>(C + (size_t)(row + 8) * N + col) =
                make_float2(acc[mt][nt][2] + bx, acc[mt][nt][3] + by);
        }
    }
}

__global__ __launch_bounds__(256)
void qkv_gemm_kernel(const float* __restrict__ x,
                     const float* __restrict__ W,
                     const float* __restrict__ b) {
    gemm_tc_body(x, W, b, g_qkv, N_QKV, C_DIM);
}

__global__ __launch_bounds__(256)
void out_gemm_kernel(const float* __restrict__ W,
                     const float* __restrict__ b,
                     float* __restrict__ out) {
    gemm_tc_body(g_y, W, b, out, C_DIM, C_DIM);
}

// ---------------------------------------------------------------------------
// RoPE sin/cos table (fp64 precision, tiny grid)
// ---------------------------------------------------------------------------
__global__ __launch_bounds__(256)
void rope_table_kernel() {
    int idx = blockIdx.x * 256 + threadIdx.x;
    if (idx >= L_SEQ * 32) return;
    int fi = idx & 31;
    int l  = idx >> 5;
    double invd = exp((double)fi * -0.28782313662425565);   // -ln(10000)/32
    double ang  = (double)l * invd;
    g_cs[l][fi] = (float)cos(ang);
    g_sn[l][fi] = (float)sin(ang);
}

// ---------------------------------------------------------------------------
// RoPE + transpose: g_qkv -> g_qT/g_kT in (bh, d, L) layout.
// ---------------------------------------------------------------------------
__global__ __launch_bounds__(256)
void rope_transpose_kernel() {
    __shared__ float Tq[DH][65];
    __shared__ float Tk[DH][65];

    const int tid = threadIdx.x;
    const int l0 = blockIdx.x * 64;
    const int bh = blockIdx.y;
    const int b  = bh >> 4;
    const int h  = bh & 15;

#pragma unroll
    for (int p = 0; p < 16; p++) {
        int e = p * 256 + tid;
        int l = e >> 6;
        int d = e & 63;
        int row  = b * L_SEQ + l0 + l;
        int base = row * N_QKV + h * DH;

        float qv = g_qkv[base + d];
        float kv = g_qkv[base + C_DIM + d];
        int d2 = (d < 32) ? d + 32 : d - 32;
        float qr = (d < 32) ? -g_qkv[base + d2] : g_qkv[base + d2];
        float kr = (d < 32) ? -g_qkv[base + C_DIM + d2] : g_qkv[base + C_DIM + d2];

        float cs = g_cs[l0 + l][d & 31];
        float sn = g_sn[l0 + l][d & 31];

        Tq[d][l] = fmaf(qv, cs, qr * sn);
        Tk[d][l] = fmaf(kv, cs, kr * sn);
    }
    __syncthreads();

    float* qout = g_qT + (size_t)bh * DH * L_SEQ;
    float* kout = g_kT + (size_t)bh * DH * L_SEQ;
#pragma unroll
    for (int p = 0; p < 16; p++) {
        int e = p * 256 + tid;
        int d = e >> 6;
        int l = e & 63;
        qout[d * L_SEQ + l0 + l] = Tq[d][l];
        kout[d * L_SEQ + l0 + l] = Tk[d][l];
    }
}

// ---------------------------------------------------------------------------
// Flash attention, 2-stage tiled (fp32 SIMT). Unchanged from Round 2.
// ---------------------------------------------------------------------------
__global__ __launch_bounds__(256)
void flash_attn_kernel(const unsigned char* __restrict__ pad) {
    __shared__ float Qs[DH * 64];
    __shared__ float KP[DH * 64];
    __shared__ float Vs[64 * DH];

    const int tid = threadIdx.x;
    const int tx = tid & 15;
    const int ty = tid >> 4;
    const int i0 = ty * 4;
    const int j0 = tx * 4;

    const int qt = blockIdx.x;
    const int bh = blockIdx.y;
    const int b  = bh >> 4;
    const int h  = bh & 15;
    const int q0 = qt * 64;

    const float* qTb = g_qT + (size_t)bh * DH * L_SEQ;
    const float* kTb = g_kT + (size_t)bh * DH * L_SEQ;

#pragma unroll
    for (int p = 0; p < 16; p++) {
        int e = p * 256 + tid;
        int d = e >> 6;
        int q = e & 63;
        Qs[d * 64 + q] = qTb[d * L_SEQ + q0 + q] * 0.125f;
    }

    float o[4][4];
#pragma unroll
    for (int i = 0; i < 4; i++)
#pragma unroll
        for (int j = 0; j < 4; j++) o[i][j] = 0.f;
    float m_i[4] = {-INFINITY, -INFINITY, -INFINITY, -INFINITY};
    float l_i[4] = {0.f, 0.f, 0.f, 0.f};

    for (int kt = 0; kt <= qt; kt++) {
        const int k0 = kt * 64;
        __syncthreads();
#pragma unroll
        for (int p = 0; p < 16; p++) {
            int e = p * 256 + tid;
            int d = e >> 6;
            int k = e & 63;
            KP[d * 64 + k] = kTb[d * L_SEQ + k0 + k];
        }
#pragma unroll
        for (int p = 0; p < 4; p++) {
            int idx = p * 256 + tid;
            int j  = idx >> 4;
            int dq = (idx & 15) * 4;
            *reinterpret_cast<float4*>(&Vs[j * DH + dq]) =
                *reinterpret_cast<const float4*>(
                    g_qkv + (size_t)(b * L_SEQ + k0 + j) * N_QKV + 2 * C_DIM + h * DH + dq);
        }
        __syncthreads();

        float s[4][4];
#pragma unroll
        for (int i = 0; i < 4; i++)
#pragma unroll
            for (int j = 0; j < 4; j++) s[i][j] = 0.f;
#pragma unroll 8
        for (int d = 0; d < DH; d++) {
            float4 q4 = *reinterpret_cast<const float4*>(&Qs[d * 64 + i0]);
            float4 k4 = *reinterpret_cast<const float4*>(&KP[d * 64 + j0]);
            float qa[4] = {q4.x, q4.y, q4.z, q4.w};
            float ka[4] = {k4.x, k4.y, k4.z, k4.w};
#pragma unroll
            for (int i = 0; i < 4; i++)
#pragma unroll
                for (int j = 0; j < 4; j++)
                    s[i][j] = fmaf(qa[i], ka[j], s[i][j]);
        }

        uchar4 pb = *reinterpret_cast<const uchar4*>(pad + b * L_SEQ + k0 + j0);
        unsigned char pv[4] = {pb.x, pb.y, pb.z, pb.w};
        if (kt == qt) {
#pragma unroll
            for (int i = 0; i < 4; i++)
#pragma unroll
                for (int j = 0; j < 4; j++)
                    if ((j0 + j > i0 + i) || pv[j]) s[i][j] = -INFINITY;
        } else {
#pragma unroll
            for (int i = 0; i < 4; i++)
#pragma unroll
                for (int j = 0; j < 4; j++)
                    if (pv[j]) s[i][j] = -INFINITY;
        }

        float corr[4];
#pragma unroll
        for (int i = 0; i < 4; i++) {
            float mt = fmaxf(fmaxf(s[i][0], s[i][1]), fmaxf(s[i][2], s[i][3]));
#pragma unroll
            for (int off = 8; off >= 1; off >>= 1)
                mt = fmaxf(mt, __shfl_xor_sync(0xffffffffu, mt, off, 16));
            float mnew = fmaxf(m_i[i], mt);
            corr[i] = __expf(m_i[i] - mnew);
            m_i[i] = mnew;
            float rs = 0.f;
#pragma unroll
            for (int j = 0; j < 4; j++) {
                float p = __expf(s[i][j] - mnew);
                s[i][j] = p;
                rs += p;
            }
#pragma unroll
            for (int off = 8; off >= 1; off >>= 1)
                rs += __shfl_xor_sync(0xffffffffu, rs, off, 16);
            l_i[i] = l_i[i] * corr[i] + rs;
#pragma unroll
            for (int j = 0; j < 4; j++) o[i][j] *= corr[i];
        }

        __syncthreads();
#pragma unroll
        for (int i = 0; i < 4; i++) {
            float4 p4 = make_float4(s[i][0], s[i][1], s[i][2], s[i][3]);
            *reinterpret_cast<float4*>(&KP[(i0 + i) * 64 + j0]) = p4;
        }
        __syncthreads();

#pragma unroll
        for (int j4 = 0; j4 < 16; j4++) {
            float4 pq[4];
#pragma unroll
            for (int i = 0; i < 4; i++)
                pq[i] = *reinterpret_cast<const float4*>(&KP[(i0 + i) * 64 + j4 * 4]);
#pragma unroll
            for (int jj = 0; jj < 4; jj++) {
                float4 v4 = *reinterpret_cast<const float4*>(&Vs[(j4 * 4 + jj) * DH + j0]);
                float pv4[4] = {((const float*)&pq[0])[jj], ((const float*)&pq[1])[jj],
                                ((const float*)&pq[2])[jj], ((const float*)&pq[3])[jj]};
#pragma unroll
                for (int i = 0; i < 4; i++) {
                    o[i][0] = fmaf(pv4[i], v4.x, o[i][0]);
                    o[i][1] = fmaf(pv4[i], v4.y, o[i][1]);
                    o[i][2] = fmaf(pv4[i], v4.z, o[i][2]);
                    o[i][3] = fmaf(pv4[i], v4.w, o[i][3]);
                }
            }
        }
    }

#pragma unroll
    for (int i = 0; i < 4; i++) {
        float inv = 1.f / l_i[i];
        float4 r = make_float4(o[i][0] * inv, o[i][1] * inv, o[i][2] * inv, o[i][3] * inv);
        int q = q0 + i0 + i;
        *reinterpret_cast<float4*>(
            g_y + (size_t)(b * L_SEQ + q) * C_DIM + h * DH + j0) = r;
    }
}

// ---------------------------------------------------------------------------
// Launch
// ---------------------------------------------------------------------------
extern "C" void kernel_launch(void* const* d_in, const int* in_sizes, int n_in,
                              void* d_out, int out_size) {
    const float*         x    = (const float*)d_in[0];
    const unsigned char* pad  = (const unsigned char*)d_in[1];
    const float*         Wqkv = (const float*)d_in[2];
    const float*         bqkv = (const float*)d_in[3];
    const float*         Wout = (const float*)d_in[4];
    const float*         bout = (const float*)d_in[5];
    float*               out  = (float*)d_out;

    rope_table_kernel<<<(L_SEQ * 32 + 255) / 256, 256>>>();

    dim3 g1(N_QKV / 128, M_ROWS / 128);
    qkv_gemm_kernel<<<g1, 256>>>(x, Wqkv, bqkv);

    dim3 gr(L_SEQ / 64, BH_NUM);
    rope_transpose_kernel<<<gr, 256>>>();

    dim3 ga(L_SEQ / 64, BH_NUM);
    flash_attn_kernel<<<ga, 256>>>(pad);

    dim3 g2(C_DIM / 128, M_ROWS / 128);
    out_gemm_kernel<<<g2, 256>>>(Wout, bout, out);
}

// round 4
// speedup vs baseline: 5.0160x; 1.4937x over previous
#include <cuda_runtime.h>
#include <cuda_bf16.h>
#include <math.h>

// Problem constants
#define B_SZ   4
#define L_SEQ  2048
#define C_DIM  1024
#define H_NUM  16
#define DH     64
#define M_ROWS (B_SZ * L_SEQ)          // 8192
#define N_QKV  (3 * C_DIM)             // 3072
#define BH_NUM (B_SZ * H_NUM)          // 64

// ---------------------------------------------------------------------------
// Static device scratch
// ---------------------------------------------------------------------------
__device__ float g_qkv[M_ROWS * N_QKV];              // (B*L, 3C)
__device__ float g_q [BH_NUM * L_SEQ * DH];          // (bh, l, d)  row-major
__device__ float g_kT[BH_NUM * DH * L_SEQ];          // (bh, d, L)  transposed
__device__ float g_y[M_ROWS * C_DIM];                // (B*L, C)
__device__ float g_cs[L_SEQ][32];                    // RoPE cos table
__device__ float g_sn[L_SEQ][32];                    // RoPE sin table

// ---------------------------------------------------------------------------
// tf32 helpers
// ---------------------------------------------------------------------------
__device__ __forceinline__ unsigned f2tf(float f) {
    unsigned u;
    asm("cvt.rna.tf32.f32 %0, %1;" : "=r"(u) : "f"(f));
    return u;
}

__device__ __forceinline__ void mma_tf32(float* c, const unsigned* a, const unsigned* b) {
    asm("mma.sync.aligned.m16n8k8.row.col.f32.tf32.tf32.f32 "
        "{%0,%1,%2,%3}, {%4,%5,%6,%7}, {%8,%9}, {%0,%1,%2,%3};"
        : "+f"(c[0]), "+f"(c[1]), "+f"(c[2]), "+f"(c[3])
        : "r"(a[0]), "r"(a[1]), "r"(a[2]), "r"(a[3]), "r"(b[0]), "r"(b[1]));
}

// ---------------------------------------------------------------------------
// tf32 tensor-core GEMM + bias (unchanged from Round 3)
// ---------------------------------------------------------------------------
#define AS_STRIDE 20
#define BS_STRIDE 136

__device__ __forceinline__ void gemm_tc_body(const float* __restrict__ A,
                                             const float* __restrict__ Bm,
                                             const float* __restrict__ bias,
                                             float* __restrict__ C,
                                             int N, int K) {
    __shared__ unsigned As[2][128 * AS_STRIDE];
    __shared__ unsigned Bs[2][16 * BS_STRIDE];

    const int tid  = threadIdx.x;
    const int lane = tid & 31;
    const int wid  = tid >> 5;
    const int warp_m = wid & 1;
    const int warp_n = wid >> 1;
    const int grp = lane >> 2;
    const int tig = lane & 3;

    const int rowBlock = blockIdx.y * 128;
    const int colBlock = blockIdx.x * 128;

    const int ar = tid >> 1;
    const int ak = (tid & 1) * 8;
    const int kr = tid >> 4;
    const int nc = (tid & 15) * 8;
    const float* Arow = A + (size_t)(rowBlock + ar) * K + ak;
    const float* Bcol = Bm + (size_t)kr * N + colBlock + nc;

    float acc[4][4][4];
#pragma unroll
    for (int mt = 0; mt < 4; mt++)
#pragma unroll
        for (int nt = 0; nt < 4; nt++)
#pragma unroll
            for (int r = 0; r < 4; r++) acc[mt][nt][r] = 0.f;

    const int nk = K >> 4;

    {
        float4 a0 = *reinterpret_cast<const float4*>(Arow);
        float4 a1 = *reinterpret_cast<const float4*>(Arow + 4);
        float4 b0 = *reinterpret_cast<const float4*>(Bcol);
        float4 b1 = *reinterpret_cast<const float4*>(Bcol + 4);
        *reinterpret_cast<uint4*>(&As[0][ar * AS_STRIDE + ak]) =
            make_uint4(f2tf(a0.x), f2tf(a0.y), f2tf(a0.z), f2tf(a0.w));
        *reinterpret_cast<uint4*>(&As[0][ar * AS_STRIDE + ak + 4]) =
            make_uint4(f2tf(a1.x), f2tf(a1.y), f2tf(a1.z), f2tf(a1.w));
        *reinterpret_cast<uint4*>(&Bs[0][kr * BS_STRIDE + nc]) =
            make_uint4(f2tf(b0.x), f2tf(b0.y), f2tf(b0.z), f2tf(b0.w));
        *reinterpret_cast<uint4*>(&Bs[0][kr * BS_STRIDE + nc + 4]) =
            make_uint4(f2tf(b1.x), f2tf(b1.y), f2tf(b1.z), f2tf(b1.w));
    }
    __syncthreads();

    for (int kc = 0; kc < nk; kc++) {
        const int buf = kc & 1;

        float4 na0, na1, nb0, nb1;
        if (kc + 1 < nk) {
            const float* Ap = Arow + (size_t)(kc + 1) * 16;
            const float* Bp = Bcol + (size_t)(kc + 1) * 16 * N;
            na0 = *reinterpret_cast<const float4*>(Ap);
            na1 = *reinterpret_cast<const float4*>(Ap + 4);
            nb0 = *reinterpret_cast<const float4*>(Bp);
            nb1 = *reinterpret_cast<const float4*>(Bp + 4);
        }

        const unsigned* Ab = As[buf];
        const unsigned* Bb = Bs[buf];
#pragma unroll
        for (int kk = 0; kk < 16; kk += 8) {
            unsigned af[4][4];
#pragma unroll
            for (int mt = 0; mt < 4; mt++) {
                int r0 = (warp_m * 64 + mt * 16 + grp) * AS_STRIDE + kk + tig;
                af[mt][0] = Ab[r0];
                af[mt][1] = Ab[r0 + 8 * AS_STRIDE];
                af[mt][2] = Ab[r0 + 4];
                af[mt][3] = Ab[r0 + 8 * AS_STRIDE + 4];
            }
            unsigned bf[4][2];
#pragma unroll
            for (int nt = 0; nt < 4; nt++) {
                int c0 = (kk + tig) * BS_STRIDE + warp_n * 32 + nt * 8 + grp;
                bf[nt][0] = Bb[c0];
                bf[nt][1] = Bb[c0 + 4 * BS_STRIDE];
            }
#pragma unroll
            for (int mt = 0; mt < 4; mt++)
#pragma unroll
                for (int nt = 0; nt < 4; nt++)
                    mma_tf32(acc[mt][nt], af[mt], bf[nt]);
        }

        if (kc + 1 < nk) {
            const int nb = buf ^ 1;
            *reinterpret_cast<uint4*>(&As[nb][ar * AS_STRIDE + ak]) =
                make_uint4(f2tf(na0.x), f2tf(na0.y), f2tf(na0.z), f2tf(na0.w));
            *reinterpret_cast<uint4*>(&As[nb][ar * AS_STRIDE + ak + 4]) =
                make_uint4(f2tf(na1.x), f2tf(na1.y), f2tf(na1.z), f2tf(na1.w));
            *reinterpret_cast<uint4*>(&Bs[nb][kr * BS_STRIDE + nc]) =
                make_uint4(f2tf(nb0.x), f2tf(nb0.y), f2tf(nb0.z), f2tf(nb0.w));
            *reinterpret_cast<uint4*>(&Bs[nb][kr * BS_STRIDE + nc + 4]) =
                make_uint4(f2tf(nb1.x), f2tf(nb1.y), f2tf(nb1.z), f2tf(nb1.w));
        }
        __syncthreads();
    }

#pragma unroll
    for (int nt = 0; nt < 4; nt++) {
        int col = colBlock + warp_n * 32 + nt * 8 + tig * 2;
        float bx = bias[col], by = bias[col + 1];
#pragma unroll
        for (int mt = 0; mt < 4; mt++) {
            int row = rowBlock + warp_m * 64 + mt * 16 + grp;
            *reinterpret_cast<float2*>(C + (size_t)row * N + col) =
                make_float2(acc[mt][nt][0] + bx, acc[mt][nt][1] + by);
            *reinterpret_cast<float2*>(C + (size_t)(row + 8) * N + col) =
                make_float2(acc[mt][nt][2] + bx, acc[mt][nt][3] + by);
        }
    }
}

__global__ __launch_bounds__(256)
void qkv_gemm_kernel(const float* __restrict__ x,
                     const float* __restrict__ W,
                     const float* __restrict__ b) {
    gemm_tc_body(x, W, b, g_qkv, N_QKV, C_DIM);
}

__global__ __launch_bounds__(256)
void out_gemm_kernel(const float* __restrict__ W,
                     const float* __restrict__ b,
                     float* __restrict__ out) {
    gemm_tc_body(g_y, W, b, out, C_DIM, C_DIM);
}

// ---------------------------------------------------------------------------
// RoPE sin/cos table
// ---------------------------------------------------------------------------
__global__ __launch_bounds__(256)
void rope_table_kernel() {
    int idx = blockIdx.x * 256 + threadIdx.x;
    if (idx >= L_SEQ * 32) return;
    int fi = idx & 31;
    int l  = idx >> 5;
    double invd = exp((double)fi * -0.28782313662425565);
    double ang  = (double)l * invd;
    g_cs[l][fi] = (float)cos(ang);
    g_sn[l][fi] = (float)sin(ang);
}

// ---------------------------------------------------------------------------
// RoPE: Q -> g_q (bh,l,d) pre-scaled by 1/8; K -> g_kT (bh,d,L) transposed.
// ---------------------------------------------------------------------------
__global__ __launch_bounds__(256)
void rope_transpose_kernel() {
    __shared__ float Tk[DH][65];

    const int tid = threadIdx.x;
    const int l0 = blockIdx.x * 64;
    const int bh = blockIdx.y;
    const int b  = bh >> 4;
    const int h  = bh & 15;

    float* qout = g_q + (size_t)bh * L_SEQ * DH;

#pragma unroll
    for (int p = 0; p < 16; p++) {
        int e = p * 256 + tid;
        int l = e >> 6;
        int d = e & 63;
        int row  = b * L_SEQ + l0 + l;
        int base = row * N_QKV + h * DH;

        float qv = g_qkv[base + d];
        float kv = g_qkv[base + C_DIM + d];
        int d2 = (d < 32) ? d + 32 : d - 32;
        float qr = (d < 32) ? -g_qkv[base + d2] : g_qkv[base + d2];
        float kr = (d < 32) ? -g_qkv[base + C_DIM + d2] : g_qkv[base + C_DIM + d2];

        float cs = g_cs[l0 + l][d & 31];
        float sn = g_sn[l0 + l][d & 31];

        qout[(l0 + l) * DH + d] = fmaf(qv, cs, qr * sn) * 0.125f;  // pre-scaled
        Tk[d][l] = fmaf(kv, cs, kr * sn);
    }
    __syncthreads();

    float* kout = g_kT + (size_t)bh * DH * L_SEQ;
#pragma unroll
    for (int p = 0; p < 16; p++) {
        int e = p * 256 + tid;
        int d = e >> 6;
        int l = e & 63;
        kout[d * L_SEQ + l0 + l] = Tk[d][l];
    }
}

// ---------------------------------------------------------------------------
// Tensor-core flash attention. 64q x 64k tiles, 128 threads (4 warps).
// Q lives in registers as tf32 A-fragments. K staged [d][k], V staged [k][d],
// P staged through the K buffer (warp-private rows).
// ---------------------------------------------------------------------------
#define SD 68   // SMEM stride (64 + 4): conflict-free A-frag loads

__global__ __launch_bounds__(128)
void flash_attn_kernel(const unsigned char* __restrict__ pad) {
    __shared__ unsigned KP[64 * SD];   // K [d][k] tf32, then P [q][k] tf32
    __shared__ unsigned Vs[64 * SD];   // V [k][d] tf32
    __shared__ float    mb[64];        // pad-mask bias for current k tile

    const int tid  = threadIdx.x;
    const int lane = tid & 31;
    const int wid  = tid >> 5;          // 0..3: q-row group
    const int grp  = lane >> 2;         // 0..7
    const int tig  = lane & 3;          // 0..3

    const int qt = blockIdx.x;
    const int bh = blockIdx.y;
    const int b  = bh >> 4;
    const int h  = bh & 15;
    const int q0 = qt * 64;

    const float* qbase = g_q  + (size_t)bh * L_SEQ * DH;
    const float* kbase = g_kT + (size_t)bh * DH * L_SEQ;

    // ---- stage Q tile [q][d] into KP, extract A-fragments, release buffer ----
#pragma unroll
    for (int p = 0; p < 8; p++) {
        int i = p * 128 + tid;
        int row = i >> 4;
        int c4  = (i & 15) * 4;
        float4 v = *reinterpret_cast<const float4*>(qbase + (size_t)(q0 + row) * DH + c4);
        KP[row * SD + c4 + 0] = f2tf(v.x);
        KP[row * SD + c4 + 1] = f2tf(v.y);
        KP[row * SD + c4 + 2] = f2tf(v.z);
        KP[row * SD + c4 + 3] = f2tf(v.w);
    }
    __syncthreads();

    unsigned Qf[8][4];                  // 8 k-chunks of Dh
    {
        int r0 = (wid * 16 + grp) * SD;
#pragma unroll
        for (int kc = 0; kc < 8; kc++) {
            Qf[kc][0] = KP[r0 + kc * 8 + tig];
            Qf[kc][1] = KP[r0 + 8 * SD + kc * 8 + tig];
            Qf[kc][2] = KP[r0 + kc * 8 + tig + 4];
            Qf[kc][3] = KP[r0 + 8 * SD + kc * 8 + tig + 4];
        }
    }

    float Oa[8][4];
#pragma unroll
    for (int nt = 0; nt < 8; nt++)
#pragma unroll
        for (int r = 0; r < 4; r++) Oa[nt][r] = 0.f;
    float m0 = -INFINITY, m1 = -INFINITY, l0s = 0.f, l1s = 0.f;

    const int row_g0 = q0 + wid * 16 + grp;       // global q row (c0/c1)
    const int row_g1 = row_g0 + 8;                // (c2/c3)

    for (int kt = 0; kt <= qt; kt++) {
        const int k0 = kt * 64;
        __syncthreads();   // prior-tile P/V reads done before overwrite

        // ---- load K tile [d][k] and V tile [k][d] (tf32) ----
#pragma unroll
        for (int p = 0; p < 8; p++) {
            int i = p * 128 + tid;
            int row = i >> 4;
            int c4  = (i & 15) * 4;
            float4 kv = *reinterpret_cast<const float4*>(
                kbase + (size_t)row * L_SEQ + k0 + c4);
            KP[row * SD + c4 + 0] = f2tf(kv.x);
            KP[row * SD + c4 + 1] = f2tf(kv.y);
            KP[row * SD + c4 + 2] = f2tf(kv.z);
            KP[row * SD + c4 + 3] = f2tf(kv.w);
            float4 vv = *reinterpret_cast<const float4*>(
                g_qkv + (size_t)(b * L_SEQ + k0 + row) * N_QKV + 2 * C_DIM + h * DH + c4);
            Vs[row * SD + c4 + 0] = f2tf(vv.x);
            Vs[row * SD + c4 + 1] = f2tf(vv.y);
            Vs[row * SD + c4 + 2] = f2tf(vv.z);
            Vs[row * SD + c4 + 3] = f2tf(vv.w);
        }
        if (tid < 64)
            mb[tid] = pad[b * L_SEQ + k0 + tid] ? -1e30f : 0.f;
        __syncthreads();

        // ---- S = Q K^T ----
        float sacc[8][4];
#pragma unroll
        for (int nt = 0; nt < 8; nt++)
#pragma unroll
            for (int r = 0; r < 4; r++) sacc[nt][r] = 0.f;
#pragma unroll
        for (int kc = 0; kc < 8; kc++) {
            unsigned bf[8][2];
#pragma unroll
            for (int nt = 0; nt < 8; nt++) {
                int c0 = (kc * 8 + tig) * SD + nt * 8 + grp;
                bf[nt][0] = KP[c0];
                bf[nt][1] = KP[c0 + 4 * SD];
            }
#pragma unroll
            for (int nt = 0; nt < 8; nt++)
                mma_tf32(sacc[nt], Qf[kc], bf[nt]);
        }

        // ---- mask + online softmax ----
        float mx0 = -INFINITY, mx1 = -INFINITY;
#pragma unroll
        for (int nt = 0; nt < 8; nt++) {
            int c = nt * 8 + 2 * tig;
            float b0 = mb[c], b1 = mb[c + 1];
            float s0 = sacc[nt][0] + b0;
            float s1 = sacc[nt][1] + b1;
            float s2 = sacc[nt][2] + b0;
            float s3 = sacc[nt][3] + b1;
            if (kt == qt) {
                int col0 = k0 + c, col1 = col0 + 1;
                if (col0 > row_g0) s0 = -1e30f;
                if (col1 > row_g0) s1 = -1e30f;
                if (col0 > row_g1) s2 = -1e30f;
                if (col1 > row_g1) s3 = -1e30f;
            }
            sacc[nt][0] = s0; sacc[nt][1] = s1;
            sacc[nt][2] = s2; sacc[nt][3] = s3;
            mx0 = fmaxf(mx0, fmaxf(s0, s1));
            mx1 = fmaxf(mx1, fmaxf(s2, s3));
        }
        mx0 = fmaxf(mx0, __shfl_xor_sync(0xffffffffu, mx0, 1));
        mx0 = fmaxf(mx0, __shfl_xor_sync(0xffffffffu, mx0, 2));
        mx1 = fmaxf(mx1, __shfl_xor_sync(0xffffffffu, mx1, 1));
        mx1 = fmaxf(mx1, __shfl_xor_sync(0xffffffffu, mx1, 2));

        float mn0 = fmaxf(m0, mx0);
        float mn1 = fmaxf(m1, mx1);
        float corr0 = __expf(m0 - mn0);
        float corr1 = __expf(m1 - mn1);
        m0 = mn0; m1 = mn1;

        float rs0 = 0.f, rs1 = 0.f;
#pragma unroll
        for (int nt = 0; nt < 8; nt++) {
            float p0 = __expf(sacc[nt][0] - mn0);
            float p1 = __expf(sacc[nt][1] - mn0);
            float p2 = __expf(sacc[nt][2] - mn1);
            float p3 = __expf(sacc[nt][3] - mn1);
            sacc[nt][0] = p0; sacc[nt][1] = p1;
            sacc[nt][2] = p2; sacc[nt][3] = p3;
            rs0 += p0 + p1;
            rs1 += p2 + p3;
        }
        rs0 += __shfl_xor_sync(0xffffffffu, rs0, 1);
        rs0 += __shfl_xor_sync(0xffffffffu, rs0, 2);
        rs1 += __shfl_xor_sync(0xffffffffu, rs1, 1);
        rs1 += __shfl_xor_sync(0xffffffffu, rs1, 2);
        l0s = l0s * corr0 + rs0;
        l1s = l1s * corr1 + rs1;
#pragma unroll
        for (int nt = 0; nt < 8; nt++) {
            Oa[nt][0] *= corr0; Oa[nt][1] *= corr0;
            Oa[nt][2] *= corr1; Oa[nt][3] *= corr1;
        }

        // ---- stage P [q][k] into KP (all warps done reading K) ----
        __syncthreads();
        {
            int r0w = (wid * 16 + grp) * SD;
#pragma unroll
            for (int nt = 0; nt < 8; nt++) {
                int c = nt * 8 + 2 * tig;
                *reinterpret_cast<uint2*>(&KP[r0w + c]) =
                    make_uint2(f2tf(sacc[nt][0]), f2tf(sacc[nt][1]));
                *reinterpret_cast<uint2*>(&KP[r0w + 8 * SD + c]) =
                    make_uint2(f2tf(sacc[nt][2]), f2tf(sacc[nt][3]));
            }
        }
        __syncwarp();   // P rows are warp-private: warp-level ordering suffices

        // ---- O += P V ----
        {
            int r0w = (wid * 16 + grp) * SD;
#pragma unroll
            for (int kc = 0; kc < 8; kc++) {
                unsigned af[4];
                af[0] = KP[r0w + kc * 8 + tig];
                af[1] = KP[r0w + 8 * SD + kc * 8 + tig];
                af[2] = KP[r0w + kc * 8 + tig + 4];
                af[3] = KP[r0w + 8 * SD + kc * 8 + tig + 4];
#pragma unroll
                for (int nt = 0; nt < 8; nt++) {
                    unsigned bf[2];
                    int c0 = (kc * 8 + tig) * SD + nt * 8 + grp;
                    bf[0] = Vs[c0];
                    bf[1] = Vs[c0 + 4 * SD];
                    mma_tf32(Oa[nt], af, bf);
                }
            }
        }
    }

    // ---- epilogue ----
    float inv0 = 1.f / l0s;
    float inv1 = 1.f / l1s;
    float* y0 = g_y + (size_t)(b * L_SEQ + row_g0) * C_DIM + h * DH;
    float* y1 = g_y + (size_t)(b * L_SEQ + row_g1) * C_DIM + h * DH;
#pragma unroll
    for (int nt = 0; nt < 8; nt++) {
        int c = nt * 8 + 2 * tig;
        *reinterpret_cast<float2*>(y0 + c) =
            make_float2(Oa[nt][0] * inv0, Oa[nt][1] * inv0);
        *reinterpret_cast<float2*>(y1 + c) =
            make_float2(Oa[nt][2] * inv1, Oa[nt][3] * inv1);
    }
}

// ---------------------------------------------------------------------------
// Launch
// ---------------------------------------------------------------------------
extern "C" void kernel_launch(void* const* d_in, const int* in_sizes, int n_in,
                              void* d_out, int out_size) {
    const float*         x    = (const float*)d_in[0];
    const unsigned char* pad  = (const unsigned char*)d_in[1];
    const float*         Wqkv = (const float*)d_in[2];
    const float*         bqkv = (const float*)d_in[3];
    const float*         Wout = (const float*)d_in[4];
    const float*         bout = (const float*)d_in[5];
    float*               out  = (float*)d_out;

    rope_table_kernel<<<(L_SEQ * 32 + 255) / 256, 256>>>();

    dim3 g1(N_QKV / 128, M_ROWS / 128);
    qkv_gemm_kernel<<<g1, 256>>>(x, Wqkv, bqkv);

    dim3 gr(L_SEQ / 64, BH_NUM);
    rope_transpose_kernel<<<gr, 256>>>();

    dim3 ga(L_SEQ / 64, BH_NUM);
    flash_attn_kernel<<<ga, 128>>>(pad);

    dim3 g2(C_DIM / 128, M_ROWS / 128);
    out_gemm_kernel<<<g2, 256>>>(Wout, bout, out);
}

// round 5
// speedup vs baseline: 5.2458x; 1.0458x over previous
#include <cuda_runtime.h>
#include <cuda_bf16.h>
#include <math.h>

// Problem constants
#define B_SZ   4
#define L_SEQ  2048
#define C_DIM  1024
#define H_NUM  16
#define DH     64
#define M_ROWS (B_SZ * L_SEQ)          // 8192
#define N_QKV  (3 * C_DIM)             // 3072
#define BH_NUM (B_SZ * H_NUM)          // 64

// ---------------------------------------------------------------------------
// Static device scratch
// ---------------------------------------------------------------------------
__device__ float g_qkv[M_ROWS * N_QKV];              // (B*L, 3C)
__device__ float g_q [BH_NUM * L_SEQ * DH];          // (bh, l, d) pre-scaled
__device__ float g_kT[BH_NUM * DH * L_SEQ];          // (bh, d, L)
__device__ float g_y[M_ROWS * C_DIM];                // (B*L, C)
__device__ float g_cs[L_SEQ][32];                    // RoPE cos table
__device__ float g_sn[L_SEQ][32];                    // RoPE sin table
__device__ float g_pb[M_ROWS];                       // pad bias (0 or -1e30)

// ---------------------------------------------------------------------------
// helpers
// ---------------------------------------------------------------------------
__device__ __forceinline__ unsigned f2tf(float f) {
    unsigned u;
    asm("cvt.rna.tf32.f32 %0, %1;" : "=r"(u) : "f"(f));
    return u;
}

__device__ __forceinline__ void mma_tf32(float* c, const unsigned* a, const unsigned* b) {
    asm("mma.sync.aligned.m16n8k8.row.col.f32.tf32.tf32.f32 "
        "{%0,%1,%2,%3}, {%4,%5,%6,%7}, {%8,%9}, {%0,%1,%2,%3};"
        : "+f"(c[0]), "+f"(c[1]), "+f"(c[2]), "+f"(c[3])
        : "r"(a[0]), "r"(a[1]), "r"(a[2]), "r"(a[3]), "r"(b[0]), "r"(b[1]));
}

#define CP_ASYNC16(dst_u32, src) \
    asm volatile("cp.async.cg.shared.global [%0], [%1], 16;" :: "r"(dst_u32), "l"(src))
#define CP_COMMIT() asm volatile("cp.async.commit_group;")
#define CP_WAIT0()  asm volatile("cp.async.wait_group 0;" ::: "memory")

// ---------------------------------------------------------------------------
// tf32 tensor-core GEMM + bias (unchanged from Round 3/4)
// ---------------------------------------------------------------------------
#define AS_STRIDE 20
#define BS_STRIDE 136

__device__ __forceinline__ void gemm_tc_body(const float* __restrict__ A,
                                             const float* __restrict__ Bm,
                                             const float* __restrict__ bias,
                                             float* __restrict__ C,
                                             int N, int K) {
    __shared__ unsigned As[2][128 * AS_STRIDE];
    __shared__ unsigned Bs[2][16 * BS_STRIDE];

    const int tid  = threadIdx.x;
    const int lane = tid & 31;
    const int wid  = tid >> 5;
    const int warp_m = wid & 1;
    const int warp_n = wid >> 1;
    const int grp = lane >> 2;
    const int tig = lane & 3;

    const int rowBlock = blockIdx.y * 128;
    const int colBlock = blockIdx.x * 128;

    const int ar = tid >> 1;
    const int ak = (tid & 1) * 8;
    const int kr = tid >> 4;
    const int nc = (tid & 15) * 8;
    const float* Arow = A + (size_t)(rowBlock + ar) * K + ak;
    const float* Bcol = Bm + (size_t)kr * N + colBlock + nc;

    float acc[4][4][4];
#pragma unroll
    for (int mt = 0; mt < 4; mt++)
#pragma unroll
        for (int nt = 0; nt < 4; nt++)
#pragma unroll
            for (int r = 0; r < 4; r++) acc[mt][nt][r] = 0.f;

    const int nk = K >> 4;

    {
        float4 a0 = *reinterpret_cast<const float4*>(Arow);
        float4 a1 = *reinterpret_cast<const float4*>(Arow + 4);
        float4 b0 = *reinterpret_cast<const float4*>(Bcol);
        float4 b1 = *reinterpret_cast<const float4*>(Bcol + 4);
        *reinterpret_cast<uint4*>(&As[0][ar * AS_STRIDE + ak]) =
            make_uint4(f2tf(a0.x), f2tf(a0.y), f2tf(a0.z), f2tf(a0.w));
        *reinterpret_cast<uint4*>(&As[0][ar * AS_STRIDE + ak + 4]) =
            make_uint4(f2tf(a1.x), f2tf(a1.y), f2tf(a1.z), f2tf(a1.w));
        *reinterpret_cast<uint4*>(&Bs[0][kr * BS_STRIDE + nc]) =
            make_uint4(f2tf(b0.x), f2tf(b0.y), f2tf(b0.z), f2tf(b0.w));
        *reinterpret_cast<uint4*>(&Bs[0][kr * BS_STRIDE + nc + 4]) =
            make_uint4(f2tf(b1.x), f2tf(b1.y), f2tf(b1.z), f2tf(b1.w));
    }
    __syncthreads();

    for (int kc = 0; kc < nk; kc++) {
        const int buf = kc & 1;

        float4 na0, na1, nb0, nb1;
        if (kc + 1 < nk) {
            const float* Ap = Arow + (size_t)(kc + 1) * 16;
            const float* Bp = Bcol + (size_t)(kc + 1) * 16 * N;
            na0 = *reinterpret_cast<const float4*>(Ap);
            na1 = *reinterpret_cast<const float4*>(Ap + 4);
            nb0 = *reinterpret_cast<const float4*>(Bp);
            nb1 = *reinterpret_cast<const float4*>(Bp + 4);
        }

        const unsigned* Ab = As[buf];
        const unsigned* Bb = Bs[buf];
#pragma unroll
        for (int kk = 0; kk < 16; kk += 8) {
            unsigned af[4][4];
#pragma unroll
            for (int mt = 0; mt < 4; mt++) {
                int r0 = (warp_m * 64 + mt * 16 + grp) * AS_STRIDE + kk + tig;
                af[mt][0] = Ab[r0];
                af[mt][1] = Ab[r0 + 8 * AS_STRIDE];
                af[mt][2] = Ab[r0 + 4];
                af[mt][3] = Ab[r0 + 8 * AS_STRIDE + 4];
            }
            unsigned bf[4][2];
#pragma unroll
            for (int nt = 0; nt < 4; nt++) {
                int c0 = (kk + tig) * BS_STRIDE + warp_n * 32 + nt * 8 + grp;
                bf[nt][0] = Bb[c0];
                bf[nt][1] = Bb[c0 + 4 * BS_STRIDE];
            }
#pragma unroll
            for (int mt = 0; mt < 4; mt++)
#pragma unroll
                for (int nt = 0; nt < 4; nt++)
                    mma_tf32(acc[mt][nt], af[mt], bf[nt]);
        }

        if (kc + 1 < nk) {
            const int nb = buf ^ 1;
            *reinterpret_cast<uint4*>(&As[nb][ar * AS_STRIDE + ak]) =
                make_uint4(f2tf(na0.x), f2tf(na0.y), f2tf(na0.z), f2tf(na0.w));
            *reinterpret_cast<uint4*>(&As[nb][ar * AS_STRIDE + ak + 4]) =
                make_uint4(f2tf(na1.x), f2tf(na1.y), f2tf(na1.z), f2tf(na1.w));
            *reinterpret_cast<uint4*>(&Bs[nb][kr * BS_STRIDE + nc]) =
                make_uint4(f2tf(nb0.x), f2tf(nb0.y), f2tf(nb0.z), f2tf(nb0.w));
            *reinterpret_cast<uint4*>(&Bs[nb][kr * BS_STRIDE + nc + 4]) =
                make_uint4(f2tf(nb1.x), f2tf(nb1.y), f2tf(nb1.z), f2tf(nb1.w));
        }
        __syncthreads();
    }

#pragma unroll
    for (int nt = 0; nt < 4; nt++) {
        int col = colBlock + warp_n * 32 + nt * 8 + tig * 2;
        float bx = bias[col], by = bias[col + 1];
#pragma unroll
        for (int mt = 0; mt < 4; mt++) {
            int row = rowBlock + warp_m * 64 + mt * 16 + grp;
            *reinterpret_cast<float2*>(C + (size_t)row * N + col) =
                make_float2(acc[mt][nt][0] + bx, acc[mt][nt][1] + by);
            *reinterpret_cast<float2*>(C + (size_t)(row + 8) * N + col) =
                make_float2(acc[mt][nt][2] + bx, acc[mt][nt][3] + by);
        }
    }
}

__global__ __launch_bounds__(256)
void qkv_gemm_kernel(const float* __restrict__ x,
                     const float* __restrict__ W,
                     const float* __restrict__ b) {
    gemm_tc_body(x, W, b, g_qkv, N_QKV, C_DIM);
}

__global__ __launch_bounds__(256)
void out_gemm_kernel(const float* __restrict__ W,
                     const float* __restrict__ b,
                     float* __restrict__ out) {
    gemm_tc_body(g_y, W, b, out, C_DIM, C_DIM);
}

// ---------------------------------------------------------------------------
// RoPE sin/cos table + pad bias
// ---------------------------------------------------------------------------
__global__ __launch_bounds__(256)
void rope_table_kernel(const unsigned char* __restrict__ pad) {
    int idx = blockIdx.x * 256 + threadIdx.x;
    if (idx < M_ROWS)
        g_pb[idx] = pad[idx] ? -1e30f : 0.f;
    if (idx >= L_SEQ * 32) return;
    int fi = idx & 31;
    int l  = idx >> 5;
    double invd = exp((double)fi * -0.28782313662425565);
    double ang  = (double)l * invd;
    g_cs[l][fi] = (float)cos(ang);
    g_sn[l][fi] = (float)sin(ang);
}

// ---------------------------------------------------------------------------
// RoPE: Q -> g_q (bh,l,d) pre-scaled by 1/8; K -> g_kT (bh,d,L) transposed.
// ---------------------------------------------------------------------------
__global__ __launch_bounds__(256)
void rope_transpose_kernel() {
    __shared__ float Tk[DH][65];

    const int tid = threadIdx.x;
    const int l0 = blockIdx.x * 64;
    const int bh = blockIdx.y;
    const int b  = bh >> 4;
    const int h  = bh & 15;

    float* qout = g_q + (size_t)bh * L_SEQ * DH;

#pragma unroll
    for (int p = 0; p < 16; p++) {
        int e = p * 256 + tid;
        int l = e >> 6;
        int d = e & 63;
        int row  = b * L_SEQ + l0 + l;
        int base = row * N_QKV + h * DH;

        float qv = g_qkv[base + d];
        float kv = g_qkv[base + C_DIM + d];
        int d2 = (d < 32) ? d + 32 : d - 32;
        float qr = (d < 32) ? -g_qkv[base + d2] : g_qkv[base + d2];
        float kr = (d < 32) ? -g_qkv[base + C_DIM + d2] : g_qkv[base + C_DIM + d2];

        float cs = g_cs[l0 + l][d & 31];
        float sn = g_sn[l0 + l][d & 31];

        qout[(l0 + l) * DH + d] = fmaf(qv, cs, qr * sn) * 0.125f;
        Tk[d][l] = fmaf(kv, cs, kr * sn);
    }
    __syncthreads();

    float* kout = g_kT + (size_t)bh * DH * L_SEQ;
#pragma unroll
    for (int p = 0; p < 16; p++) {
        int e = p * 256 + tid;
        int d = e >> 6;
        int l = e & 63;
        kout[d * L_SEQ + l0 + l] = Tk[d][l];
    }
}

// ---------------------------------------------------------------------------
// Tensor-core flash attention, pipelined.
// 64q x 64k tiles, 128 threads. Q as register A-frags (direct LDG),
// K/V cp.async double-buffered raw fp32 (mma truncates to tf32),
// P converted C-frag -> A-frag via shuffles (no SMEM round trip).
// One wait_group + one __syncthreads per tile.
// ---------------------------------------------------------------------------
#define SD 68                         // 68 mod 32 = 4 -> conflict-free frags
#define FA_SMEM (2 * 2 * 64 * SD * 4) // 69632 bytes

__global__ __launch_bounds__(128)
void flash_attn_kernel() {
    extern __shared__ float sm[];
    float* Ks  = sm;                   // [2][64*SD]  K^T tile [d][k]
    float* Vsm = sm + 2 * 64 * SD;     // [2][64*SD]  V tile   [k][d]

    const int tid  = threadIdx.x;
    const int lane = tid & 31;
    const int wid  = tid >> 5;
    const int grp  = lane >> 2;
    const int tig  = lane & 3;

    const int qt = blockIdx.x;
    const int bh = blockIdx.y;
    const int b  = bh >> 4;
    const int h  = bh & 15;
    const int q0 = qt * 64;

    const float* kbase  = g_kT + (size_t)bh * DH * L_SEQ;
    const float* vgbase = g_qkv + (size_t)b * L_SEQ * N_QKV + 2 * C_DIM + h * DH;
    const float* pb     = g_pb + b * L_SEQ;

    // staging mapping (per thread: 8 K + 8 V 16B copies per tile)
    const int srow_base = tid >> 4;          // used as i>>4 pattern below
    (void)srow_base;

    // ---- Q fragments straight from gmem (RNA-converted) ----
    const int row_g0 = q0 + wid * 16 + grp;
    const int row_g1 = row_g0 + 8;
    unsigned Qf[8][4];
    {
        const float* q0p = g_q + ((size_t)bh * L_SEQ + row_g0) * DH;
        const float* q1p = g_q + ((size_t)bh * L_SEQ + row_g1) * DH;
#pragma unroll
        for (int kc = 0; kc < 8; kc++) {
            Qf[kc][0] = f2tf(q0p[kc * 8 + tig]);
            Qf[kc][1] = f2tf(q1p[kc * 8 + tig]);
            Qf[kc][2] = f2tf(q0p[kc * 8 + tig + 4]);
            Qf[kc][3] = f2tf(q1p[kc * 8 + tig + 4]);
        }
    }

    // ---- stage tile 0 ----
    {
#pragma unroll
        for (int p = 0; p < 8; p++) {
            int i = p * 128 + tid;
            int row = i >> 4;
            int c4  = (i & 15) * 4;
            unsigned kd = (unsigned)__cvta_generic_to_shared(&Ks[row * SD + c4]);
            CP_ASYNC16(kd, kbase + (size_t)row * L_SEQ + c4);
            unsigned vd = (unsigned)__cvta_generic_to_shared(&Vsm[row * SD + c4]);
            CP_ASYNC16(vd, vgbase + (size_t)row * N_QKV + c4);
        }
        CP_COMMIT();
    }

    float Oa[8][4];
#pragma unroll
    for (int nt = 0; nt < 8; nt++)
#pragma unroll
        for (int r = 0; r < 4; r++) Oa[nt][r] = 0.f;
    float m0 = -INFINITY, m1 = -INFINITY, l0s = 0.f, l1s = 0.f;

    const int psrc0 = (grp << 2) | (tig >> 1);   // shuffle source lanes
    const int psrc1 = psrc0 + 2;
    const bool podd = (tig & 1);

    for (int kt = 0; kt <= qt; kt++) {
        const int k0  = kt * 64;
        const int buf = kt & 1;

        CP_WAIT0();
        __syncthreads();

        // prefetch next tile while we compute
        if (kt < qt) {
            const int nb = buf ^ 1;
            const int nk0 = k0 + 64;
#pragma unroll
            for (int p = 0; p < 8; p++) {
                int i = p * 128 + tid;
                int row = i >> 4;
                int c4  = (i & 15) * 4;
                unsigned kd = (unsigned)__cvta_generic_to_shared(&Ks[nb * 64 * SD + row * SD + c4]);
                CP_ASYNC16(kd, kbase + (size_t)row * L_SEQ + nk0 + c4);
                unsigned vd = (unsigned)__cvta_generic_to_shared(&Vsm[nb * 64 * SD + row * SD + c4]);
                CP_ASYNC16(vd, vgbase + (size_t)(nk0 + row) * N_QKV + c4);
            }
            CP_COMMIT();
        }

        const float* Kb = Ks  + buf * 64 * SD;
        const float* Vb = Vsm + buf * 64 * SD;

        // ---- S = Q K^T (K bits fed raw; HW truncates to tf32) ----
        float sacc[8][4];
#pragma unroll
        for (int nt = 0; nt < 8; nt++)
#pragma unroll
            for (int r = 0; r < 4; r++) sacc[nt][r] = 0.f;
#pragma unroll
        for (int kc = 0; kc < 8; kc++) {
            unsigned bf[8][2];
#pragma unroll
            for (int nt = 0; nt < 8; nt++) {
                int c0 = (kc * 8 + tig) * SD + nt * 8 + grp;
                bf[nt][0] = __float_as_uint(Kb[c0]);
                bf[nt][1] = __float_as_uint(Kb[c0 + 4 * SD]);
            }
#pragma unroll
            for (int nt = 0; nt < 8; nt++)
                mma_tf32(sacc[nt], Qf[kc], bf[nt]);
        }

        // ---- mask + online softmax ----
        float mx0 = -INFINITY, mx1 = -INFINITY;
#pragma unroll
        for (int nt = 0; nt < 8; nt++) {
            int c = nt * 8 + 2 * tig;
            float2 pbv = *reinterpret_cast<const float2*>(&pb[k0 + c]);
            float s0 = sacc[nt][0] + pbv.x;
            float s1 = sacc[nt][1] + pbv.y;
            float s2 = sacc[nt][2] + pbv.x;
            float s3 = sacc[nt][3] + pbv.y;
            if (kt == qt) {
                int col0 = k0 + c, col1 = col0 + 1;
                if (col0 > row_g0) s0 = -1e30f;
                if (col1 > row_g0) s1 = -1e30f;
                if (col0 > row_g1) s2 = -1e30f;
                if (col1 > row_g1) s3 = -1e30f;
            }
            sacc[nt][0] = s0; sacc[nt][1] = s1;
            sacc[nt][2] = s2; sacc[nt][3] = s3;
            mx0 = fmaxf(mx0, fmaxf(s0, s1));
            mx1 = fmaxf(mx1, fmaxf(s2, s3));
        }
        mx0 = fmaxf(mx0, __shfl_xor_sync(0xffffffffu, mx0, 1));
        mx0 = fmaxf(mx0, __shfl_xor_sync(0xffffffffu, mx0, 2));
        mx1 = fmaxf(mx1, __shfl_xor_sync(0xffffffffu, mx1, 1));
        mx1 = fmaxf(mx1, __shfl_xor_sync(0xffffffffu, mx1, 2));

        float mn0 = fmaxf(m0, mx0);
        float mn1 = fmaxf(m1, mx1);
        float corr0 = __expf(m0 - mn0);
        float corr1 = __expf(m1 - mn1);
        m0 = mn0; m1 = mn1;

        float rs0 = 0.f, rs1 = 0.f;
#pragma unroll
        for (int nt = 0; nt < 8; nt++) {
            float p0 = __expf(sacc[nt][0] - mn0);
            float p1 = __expf(sacc[nt][1] - mn0);
            float p2 = __expf(sacc[nt][2] - mn1);
            float p3 = __expf(sacc[nt][3] - mn1);
            sacc[nt][0] = p0; sacc[nt][1] = p1;
            sacc[nt][2] = p2; sacc[nt][3] = p3;
            rs0 += p0 + p1;
            rs1 += p2 + p3;
        }
        rs0 += __shfl_xor_sync(0xffffffffu, rs0, 1);
        rs0 += __shfl_xor_sync(0xffffffffu, rs0, 2);
        rs1 += __shfl_xor_sync(0xffffffffu, rs1, 1);
        rs1 += __shfl_xor_sync(0xffffffffu, rs1, 2);
        l0s = l0s * corr0 + rs0;
        l1s = l1s * corr1 + rs1;
#pragma unroll
        for (int nt = 0; nt < 8; nt++) {
            Oa[nt][0] *= corr0; Oa[nt][1] *= corr0;
            Oa[nt][2] *= corr1; Oa[nt][3] *= corr1;
        }

        // ---- O += P V : C-frag -> A-frag via shuffles, no SMEM ----
#pragma unroll
        for (int kc = 0; kc < 8; kc++) {
            float v0 = __shfl_sync(0xffffffffu, sacc[kc][0], psrc0, 32);
            float v1 = __shfl_sync(0xffffffffu, sacc[kc][1], psrc0, 32);
            float v2 = __shfl_sync(0xffffffffu, sacc[kc][2], psrc0, 32);
            float v3 = __shfl_sync(0xffffffffu, sacc[kc][3], psrc0, 32);
            float w0 = __shfl_sync(0xffffffffu, sacc[kc][0], psrc1, 32);
            float w1 = __shfl_sync(0xffffffffu, sacc[kc][1], psrc1, 32);
            float w2 = __shfl_sync(0xffffffffu, sacc[kc][2], psrc1, 32);
            float w3 = __shfl_sync(0xffffffffu, sacc[kc][3], psrc1, 32);
            unsigned af[4];
            af[0] = f2tf(podd ? v1 : v0);
            af[1] = f2tf(podd ? v3 : v2);
            af[2] = f2tf(podd ? w1 : w0);
            af[3] = f2tf(podd ? w3 : w2);
#pragma unroll
            for (int nt = 0; nt < 8; nt++) {
                unsigned bf[2];
                int c0 = (kc * 8 + tig) * SD + nt * 8 + grp;
                bf[0] = __float_as_uint(Vb[c0]);
                bf[1] = __float_as_uint(Vb[c0 + 4 * SD]);
                mma_tf32(Oa[nt], af, bf);
            }
        }
    }

    // ---- epilogue ----
    float inv0 = 1.f / l0s;
    float inv1 = 1.f / l1s;
    float* y0 = g_y + (size_t)(b * L_SEQ + row_g0) * C_DIM + h * DH;
    float* y1 = g_y + (size_t)(b * L_SEQ + row_g1) * C_DIM + h * DH;
#pragma unroll
    for (int nt = 0; nt < 8; nt++) {
        int c = nt * 8 + 2 * tig;
        *reinterpret_cast<float2*>(y0 + c) =
            make_float2(Oa[nt][0] * inv0, Oa[nt][1] * inv0);
        *reinterpret_cast<float2*>(y1 + c) =
            make_float2(Oa[nt][2] * inv1, Oa[nt][3] * inv1);
    }
}

// ---------------------------------------------------------------------------
// Launch
// ---------------------------------------------------------------------------
extern "C" void kernel_launch(void* const* d_in, const int* in_sizes, int n_in,
                              void* d_out, int out_size) {
    const float*         x    = (const float*)d_in[0];
    const unsigned char* pad  = (const unsigned char*)d_in[1];
    const float*         Wqkv = (const float*)d_in[2];
    const float*         bqkv = (const float*)d_in[3];
    const float*         Wout = (const float*)d_in[4];
    const float*         bout = (const float*)d_in[5];
    float*               out  = (float*)d_out;

    cudaFuncSetAttribute(flash_attn_kernel,
                         cudaFuncAttributeMaxDynamicSharedMemorySize, FA_SMEM);

    rope_table_kernel<<<(L_SEQ * 32 + 255) / 256, 256>>>(pad);

    dim3 g1(N_QKV / 128, M_ROWS / 128);
    qkv_gemm_kernel<<<g1, 256>>>(x, Wqkv, bqkv);

    dim3 gr(L_SEQ / 64, BH_NUM);
    rope_transpose_kernel<<<gr, 256>>>();

    dim3 ga(L_SEQ / 64, BH_NUM);
    flash_attn_kernel<<<ga, 128, FA_SMEM>>>();

    dim3 g2(C_DIM / 128, M_ROWS / 128);
    out_gemm_kernel<<<g2, 256>>>(Wout, bout, out);
}

// round 6
// speedup vs baseline: 6.1722x; 1.1766x over previous
#include <cuda_runtime.h>
#include <cuda_bf16.h>
#include <math.h>

// Problem constants
#define B_SZ   4
#define L_SEQ  2048
#define C_DIM  1024
#define H_NUM  16
#define DH     64
#define M_ROWS (B_SZ * L_SEQ)          // 8192
#define N_QKV  (3 * C_DIM)             // 3072
#define BH_NUM (B_SZ * H_NUM)          // 64

// ---------------------------------------------------------------------------
// Static device scratch
// ---------------------------------------------------------------------------
__device__ float g_qkv[M_ROWS * N_QKV];              // (B*L, 3C)
__device__ float g_q [BH_NUM * L_SEQ * DH];          // (bh, l, d) pre-scaled
__device__ float g_kT[BH_NUM * DH * L_SEQ];          // (bh, d, L)
__device__ float g_y[M_ROWS * C_DIM];                // (B*L, C)
__device__ float g_cs[L_SEQ][32];                    // RoPE cos table
__device__ float g_sn[L_SEQ][32];                    // RoPE sin table
__device__ float g_pb[M_ROWS];                       // pad bias (0 or -1e30)

// ---------------------------------------------------------------------------
// helpers
// ---------------------------------------------------------------------------
__device__ __forceinline__ unsigned f2tf(float f) {
    unsigned u;
    asm("cvt.rna.tf32.f32 %0, %1;" : "=r"(u) : "f"(f));
    return u;
}

__device__ __forceinline__ void mma_tf32(float* c, const unsigned* a, const unsigned* b) {
    asm("mma.sync.aligned.m16n8k8.row.col.f32.tf32.tf32.f32 "
        "{%0,%1,%2,%3}, {%4,%5,%6,%7}, {%8,%9}, {%0,%1,%2,%3};"
        : "+f"(c[0]), "+f"(c[1]), "+f"(c[2]), "+f"(c[3])
        : "r"(a[0]), "r"(a[1]), "r"(a[2]), "r"(a[3]), "r"(b[0]), "r"(b[1]));
}

__device__ __forceinline__ unsigned smaddr(const void* p) {
    return (unsigned)__cvta_generic_to_shared(p);
}

#define CP_ASYNC16(dst_u32, src) \
    asm volatile("cp.async.cg.shared.global [%0], [%1], 16;" :: "r"(dst_u32), "l"(src))
#define CP_COMMIT() asm volatile("cp.async.commit_group;")
#define CP_WAIT0()  asm volatile("cp.async.wait_group 0;" ::: "memory")

// ---------------------------------------------------------------------------
// tf32 GEMM + bias. 128x128x16 tile, 8 warps (2m x 4n), warp tile 64x32.
// cp.async raw-fp32 double-buffered staging; RNA tf32 convert at frag load.
// ---------------------------------------------------------------------------
#define AS_STRIDE 20
#define BS_STRIDE 136

__device__ __forceinline__ void gemm_tc_body(const float* __restrict__ A,
                                             const float* __restrict__ Bm,
                                             const float* __restrict__ bias,
                                             float* __restrict__ C,
                                             int N, int K) {
    __shared__ float As[2][128 * AS_STRIDE];   // raw fp32
    __shared__ float Bs[2][16 * BS_STRIDE];

    const int tid  = threadIdx.x;
    const int lane = tid & 31;
    const int wid  = tid >> 5;
    const int warp_m = wid & 1;
    const int warp_n = wid >> 1;
    const int grp = lane >> 2;
    const int tig = lane & 3;

    const int rowBlock = blockIdx.y * 128;
    const int colBlock = blockIdx.x * 128;
    const float* Abase = A + (size_t)rowBlock * K;

    float acc[4][4][4];
#pragma unroll
    for (int mt = 0; mt < 4; mt++)
#pragma unroll
        for (int nt = 0; nt < 4; nt++)
#pragma unroll
            for (int r = 0; r < 4; r++) acc[mt][nt][r] = 0.f;

    const int nk = K >> 4;

    // ---- stage 0 ----
#pragma unroll
    for (int p = 0; p < 2; p++) {
        int c = p * 256 + tid;
        int row = c >> 2, k4 = (c & 3) * 4;
        CP_ASYNC16(smaddr(&As[0][row * AS_STRIDE + k4]),
                   Abase + (size_t)row * K + k4);
        int kr = c >> 5, n4 = (c & 31) * 4;
        CP_ASYNC16(smaddr(&Bs[0][kr * BS_STRIDE + n4]),
                   Bm + (size_t)kr * N + colBlock + n4);
    }
    CP_COMMIT();

    for (int kc = 0; kc < nk; kc++) {
        const int buf = kc & 1;
        CP_WAIT0();
        __syncthreads();

        if (kc + 1 < nk) {
            const int nb = buf ^ 1;
            const int kof = (kc + 1) * 16;
#pragma unroll
            for (int p = 0; p < 2; p++) {
                int c = p * 256 + tid;
                int row = c >> 2, k4 = (c & 3) * 4;
                CP_ASYNC16(smaddr(&As[nb][row * AS_STRIDE + k4]),
                           Abase + (size_t)row * K + kof + k4);
                int kr = c >> 5, n4 = (c & 31) * 4;
                CP_ASYNC16(smaddr(&Bs[nb][kr * BS_STRIDE + n4]),
                           Bm + (size_t)(kof + kr) * N + colBlock + n4);
            }
            CP_COMMIT();
        }

        const float* Ab = As[buf];
        const float* Bb = Bs[buf];
#pragma unroll
        for (int kk = 0; kk < 16; kk += 8) {
            unsigned af[4][4];
#pragma unroll
            for (int mt = 0; mt < 4; mt++) {
                int r0 = (warp_m * 64 + mt * 16 + grp) * AS_STRIDE + kk + tig;
                af[mt][0] = f2tf(Ab[r0]);
                af[mt][1] = f2tf(Ab[r0 + 8 * AS_STRIDE]);
                af[mt][2] = f2tf(Ab[r0 + 4]);
                af[mt][3] = f2tf(Ab[r0 + 8 * AS_STRIDE + 4]);
            }
            unsigned bf[4][2];
#pragma unroll
            for (int nt = 0; nt < 4; nt++) {
                int c0 = (kk + tig) * BS_STRIDE + warp_n * 32 + nt * 8 + grp;
                bf[nt][0] = f2tf(Bb[c0]);
                bf[nt][1] = f2tf(Bb[c0 + 4 * BS_STRIDE]);
            }
#pragma unroll
            for (int mt = 0; mt < 4; mt++)
#pragma unroll
                for (int nt = 0; nt < 4; nt++)
                    mma_tf32(acc[mt][nt], af[mt], bf[nt]);
        }
        __syncthreads();
    }

#pragma unroll
    for (int nt = 0; nt < 4; nt++) {
        int col = colBlock + warp_n * 32 + nt * 8 + tig * 2;
        float bx = bias[col], by = bias[col + 1];
#pragma unroll
        for (int mt = 0; mt < 4; mt++) {
            int row = rowBlock + warp_m * 64 + mt * 16 + grp;
            *reinterpret_cast<float2*>(C + (size_t)row * N + col) =
                make_float2(acc[mt][nt][0] + bx, acc[mt][nt][1] + by);
            *reinterpret_cast<float2*>(C + (size_t)(row + 8) * N + col) =
                make_float2(acc[mt][nt][2] + bx, acc[mt][nt][3] + by);
        }
    }
}

__global__ __launch_bounds__(256)
void qkv_gemm_kernel(const float* __restrict__ x,
                     const float* __restrict__ W,
                     const float* __restrict__ b) {
    gemm_tc_body(x, W, b, g_qkv, N_QKV, C_DIM);
}

__global__ __launch_bounds__(256)
void out_gemm_kernel(const float* __restrict__ W,
                     const float* __restrict__ b,
                     float* __restrict__ out) {
    gemm_tc_body(g_y, W, b, out, C_DIM, C_DIM);
}

// ---------------------------------------------------------------------------
// RoPE sin/cos table + pad bias
// ---------------------------------------------------------------------------
__global__ __launch_bounds__(256)
void rope_table_kernel(const unsigned char* __restrict__ pad) {
    int idx = blockIdx.x * 256 + threadIdx.x;
    if (idx < M_ROWS)
        g_pb[idx] = pad[idx] ? -1e30f : 0.f;
    if (idx >= L_SEQ * 32) return;
    int fi = idx & 31;
    int l  = idx >> 5;
    double invd = exp((double)fi * -0.28782313662425565);
    double ang  = (double)l * invd;
    g_cs[l][fi] = (float)cos(ang);
    g_sn[l][fi] = (float)sin(ang);
}

// ---------------------------------------------------------------------------
// RoPE: Q -> g_q (bh,l,d) pre-scaled by 1/8; K -> g_kT (bh,d,L) transposed.
// ---------------------------------------------------------------------------
__global__ __launch_bounds__(256)
void rope_transpose_kernel() {
    __shared__ float Tk[DH][65];

    const int tid = threadIdx.x;
    const int l0 = blockIdx.x * 64;
    const int bh = blockIdx.y;
    const int b  = bh >> 4;
    const int h  = bh & 15;

    float* qout = g_q + (size_t)bh * L_SEQ * DH;

#pragma unroll
    for (int p = 0; p < 16; p++) {
        int e = p * 256 + tid;
        int l = e >> 6;
        int d = e & 63;
        int row  = b * L_SEQ + l0 + l;
        int base = row * N_QKV + h * DH;

        float qv = g_qkv[base + d];
        float kv = g_qkv[base + C_DIM + d];
        int d2 = (d < 32) ? d + 32 : d - 32;
        float qr = (d < 32) ? -g_qkv[base + d2] : g_qkv[base + d2];
        float kr = (d < 32) ? -g_qkv[base + C_DIM + d2] : g_qkv[base + C_DIM + d2];

        float cs = g_cs[l0 + l][d & 31];
        float sn = g_sn[l0 + l][d & 31];

        qout[(l0 + l) * DH + d] = fmaf(qv, cs, qr * sn) * 0.125f;
        Tk[d][l] = fmaf(kv, cs, kr * sn);
    }
    __syncthreads();

    float* kout = g_kT + (size_t)bh * DH * L_SEQ;
#pragma unroll
    for (int p = 0; p < 16; p++) {
        int e = p * 256 + tid;
        int d = e >> 6;
        int l = e & 63;
        kout[d * L_SEQ + l0 + l] = Tk[d][l];
    }
}

// ---------------------------------------------------------------------------
// Tensor-core flash attention, 128q x 64k tiles, 128 threads (4 warps),
// 32 q-rows per warp (mt=2) -> K/V B-fragments reused across 2 MMAs.
// Q staged in SMEM (cp.async) once per block; K/V cp.async double-buffered.
// ---------------------------------------------------------------------------
#define SD 68
#define KV_WORDS (64 * SD)                         // 4352 per buffer
#define Q_WORDS  (128 * SD)                        // 8704
#define FA_SMEM  ((Q_WORDS + 4 * KV_WORDS) * 4)    // 104448 bytes

__global__ __launch_bounds__(128)
void flash_attn_kernel() {
    extern __shared__ float sm[];
    float* Qs  = sm;                               // [128][SD]
    float* Ks  = sm + Q_WORDS;                     // [2][64*SD]
    float* Vsm = Ks + 2 * KV_WORDS;                // [2][64*SD]

    const int tid  = threadIdx.x;
    const int lane = tid & 31;
    const int wid  = tid >> 5;
    const int grp  = lane >> 2;
    const int tig  = lane & 3;

    const int qtb = (gridDim.x - 1) - blockIdx.x;  // big tiles first
    const int bh  = blockIdx.y;
    const int b   = bh >> 4;
    const int h   = bh & 15;
    const int q0  = qtb * 128;

    const float* qgbase = g_q  + ((size_t)bh * L_SEQ + q0) * DH;
    const float* kbase  = g_kT + (size_t)bh * DH * L_SEQ;
    const float* vgbase = g_qkv + (size_t)b * L_SEQ * N_QKV + 2 * C_DIM + h * DH;
    const float* pb     = g_pb + b * L_SEQ;

    // ---- stage Q (128x64) + first K/V tile, one commit group ----
#pragma unroll
    for (int p = 0; p < 16; p++) {
        int c = p * 128 + tid;
        int row = c >> 4, c4 = (c & 15) * 4;
        CP_ASYNC16(smaddr(&Qs[row * SD + c4]), qgbase + (size_t)row * DH + c4);
    }
#pragma unroll
    for (int p = 0; p < 8; p++) {
        int i = p * 128 + tid;
        int row = i >> 4, c4 = (i & 15) * 4;
        CP_ASYNC16(smaddr(&Ks[row * SD + c4]), kbase + (size_t)row * L_SEQ + c4);
        CP_ASYNC16(smaddr(&Vsm[row * SD + c4]), vgbase + (size_t)row * N_QKV + c4);
    }
    CP_COMMIT();

    float Oa[2][8][4];
#pragma unroll
    for (int mt = 0; mt < 2; mt++)
#pragma unroll
        for (int nt = 0; nt < 8; nt++)
#pragma unroll
            for (int r = 0; r < 4; r++) Oa[mt][nt][r] = 0.f;
    float mA[2] = {-INFINITY, -INFINITY};   // rows grp
    float mB[2] = {-INFINITY, -INFINITY};   // rows grp+8
    float lA[2] = {0.f, 0.f};
    float lB[2] = {0.f, 0.f};

    int rg0[2], rg1[2];
#pragma unroll
    for (int mt = 0; mt < 2; mt++) {
        rg0[mt] = q0 + wid * 32 + mt * 16 + grp;
        rg1[mt] = rg0[mt] + 8;
    }
    const int qrow_loc0 = wid * 32;           // local base row for this warp

    const int psrc0 = (grp << 2) | (tig >> 1);
    const int psrc1 = psrc0 + 2;
    const bool podd = (tig & 1);

    const int nkt = 2 * qtb + 2;

    for (int kt = 0; kt < nkt; kt++) {
        const int k0  = kt * 64;
        const int buf = kt & 1;

        CP_WAIT0();
        __syncthreads();

        if (kt + 1 < nkt) {
            const int nb = buf ^ 1;
            const int nk0 = k0 + 64;
#pragma unroll
            for (int p = 0; p < 8; p++) {
                int i = p * 128 + tid;
                int row = i >> 4, c4 = (i & 15) * 4;
                CP_ASYNC16(smaddr(&Ks[nb * KV_WORDS + row * SD + c4]),
                           kbase + (size_t)row * L_SEQ + nk0 + c4);
                CP_ASYNC16(smaddr(&Vsm[nb * KV_WORDS + row * SD + c4]),
                           vgbase + (size_t)(nk0 + row) * N_QKV + c4);
            }
            CP_COMMIT();
        }

        const float* Kb = Ks  + buf * KV_WORDS;
        const float* Vb = Vsm + buf * KV_WORDS;

        // ---- S = Q K^T : B-frags loaded once per kc, reused across mt ----
        float sacc[2][8][4];
#pragma unroll
        for (int mt = 0; mt < 2; mt++)
#pragma unroll
            for (int nt = 0; nt < 8; nt++)
#pragma unroll
                for (int r = 0; r < 4; r++) sacc[mt][nt][r] = 0.f;

#pragma unroll
        for (int kc = 0; kc < 8; kc++) {
            unsigned bf[8][2];
#pragma unroll
            for (int nt = 0; nt < 8; nt++) {
                int c0 = (kc * 8 + tig) * SD + nt * 8 + grp;
                bf[nt][0] = __float_as_uint(Kb[c0]);
                bf[nt][1] = __float_as_uint(Kb[c0 + 4 * SD]);
            }
#pragma unroll
            for (int mt = 0; mt < 2; mt++) {
                int r0 = (qrow_loc0 + mt * 16 + grp) * SD + kc * 8 + tig;
                unsigned af[4];
                af[0] = f2tf(Qs[r0]);
                af[1] = f2tf(Qs[r0 + 8 * SD]);
                af[2] = f2tf(Qs[r0 + 4]);
                af[3] = f2tf(Qs[r0 + 8 * SD + 4]);
#pragma unroll
                for (int nt = 0; nt < 8; nt++)
                    mma_tf32(sacc[mt][nt], af, bf[nt]);
            }
        }

        // ---- mask + online softmax (per mt) ----
        const bool diag = (kt >= 2 * qtb);
#pragma unroll
        for (int mt = 0; mt < 2; mt++) {
            float mx0 = -INFINITY, mx1 = -INFINITY;
#pragma unroll
            for (int nt = 0; nt < 8; nt++) {
                int c = nt * 8 + 2 * tig;
                float2 pbv = *reinterpret_cast<const float2*>(&pb[k0 + c]);
                float s0 = sacc[mt][nt][0] + pbv.x;
                float s1 = sacc[mt][nt][1] + pbv.y;
                float s2 = sacc[mt][nt][2] + pbv.x;
                float s3 = sacc[mt][nt][3] + pbv.y;
                if (diag) {
                    int col0 = k0 + c, col1 = col0 + 1;
                    if (col0 > rg0[mt]) s0 = -1e30f;
                    if (col1 > rg0[mt]) s1 = -1e30f;
                    if (col0 > rg1[mt]) s2 = -1e30f;
                    if (col1 > rg1[mt]) s3 = -1e30f;
                }
                sacc[mt][nt][0] = s0; sacc[mt][nt][1] = s1;
                sacc[mt][nt][2] = s2; sacc[mt][nt][3] = s3;
                mx0 = fmaxf(mx0, fmaxf(s0, s1));
                mx1 = fmaxf(mx1, fmaxf(s2, s3));
            }
            mx0 = fmaxf(mx0, __shfl_xor_sync(0xffffffffu, mx0, 1));
            mx0 = fmaxf(mx0, __shfl_xor_sync(0xffffffffu, mx0, 2));
            mx1 = fmaxf(mx1, __shfl_xor_sync(0xffffffffu, mx1, 1));
            mx1 = fmaxf(mx1, __shfl_xor_sync(0xffffffffu, mx1, 2));

            float mn0 = fmaxf(mA[mt], mx0);
            float mn1 = fmaxf(mB[mt], mx1);
            float corr0 = __expf(mA[mt] - mn0);
            float corr1 = __expf(mB[mt] - mn1);
            mA[mt] = mn0; mB[mt] = mn1;

            float rs0 = 0.f, rs1 = 0.f;
#pragma unroll
            for (int nt = 0; nt < 8; nt++) {
                float p0 = __expf(sacc[mt][nt][0] - mn0);
                float p1 = __expf(sacc[mt][nt][1] - mn0);
                float p2 = __expf(sacc[mt][nt][2] - mn1);
                float p3 = __expf(sacc[mt][nt][3] - mn1);
                sacc[mt][nt][0] = p0; sacc[mt][nt][1] = p1;
                sacc[mt][nt][2] = p2; sacc[mt][nt][3] = p3;
                rs0 += p0 + p1;
                rs1 += p2 + p3;
            }
            rs0 += __shfl_xor_sync(0xffffffffu, rs0, 1);
            rs0 += __shfl_xor_sync(0xffffffffu, rs0, 2);
            rs1 += __shfl_xor_sync(0xffffffffu, rs1, 1);
            rs1 += __shfl_xor_sync(0xffffffffu, rs1, 2);
            lA[mt] = lA[mt] * corr0 + rs0;
            lB[mt] = lB[mt] * corr1 + rs1;
#pragma unroll
            for (int nt = 0; nt < 8; nt++) {
                Oa[mt][nt][0] *= corr0; Oa[mt][nt][1] *= corr0;
                Oa[mt][nt][2] *= corr1; Oa[mt][nt][3] *= corr1;
            }
        }

        // ---- O += P V : V B-frags loaded once per kc, reused across mt ----
#pragma unroll
        for (int kc = 0; kc < 8; kc++) {
            unsigned bf[8][2];
#pragma unroll
            for (int nt = 0; nt < 8; nt++) {
                int c0 = (kc * 8 + tig) * SD + nt * 8 + grp;
                bf[nt][0] = __float_as_uint(Vb[c0]);
                bf[nt][1] = __float_as_uint(Vb[c0 + 4 * SD]);
            }
#pragma unroll
            for (int mt = 0; mt < 2; mt++) {
                float v0 = __shfl_sync(0xffffffffu, sacc[mt][kc][0], psrc0, 32);
                float v1 = __shfl_sync(0xffffffffu, sacc[mt][kc][1], psrc0, 32);
                float v2 = __shfl_sync(0xffffffffu, sacc[mt][kc][2], psrc0, 32);
                float v3 = __shfl_sync(0xffffffffu, sacc[mt][kc][3], psrc0, 32);
                float w0 = __shfl_sync(0xffffffffu, sacc[mt][kc][0], psrc1, 32);
                float w1 = __shfl_sync(0xffffffffu, sacc[mt][kc][1], psrc1, 32);
                float w2 = __shfl_sync(0xffffffffu, sacc[mt][kc][2], psrc1, 32);
                float w3 = __shfl_sync(0xffffffffu, sacc[mt][kc][3], psrc1, 32);
                unsigned af[4];
                af[0] = f2tf(podd ? v1 : v0);
                af[1] = f2tf(podd ? v3 : v2);
                af[2] = f2tf(podd ? w1 : w0);
                af[3] = f2tf(podd ? w3 : w2);
#pragma unroll
                for (int nt = 0; nt < 8; nt++)
                    mma_tf32(Oa[mt][nt], af, bf[nt]);
            }
        }
    }

    // ---- epilogue ----
#pragma unroll
    for (int mt = 0; mt < 2; mt++) {
        float inv0 = 1.f / lA[mt];
        float inv1 = 1.f / lB[mt];
        float* y0 = g_y + (size_t)(b * L_SEQ + rg0[mt]) * C_DIM + h * DH;
        float* y1 = g_y + (size_t)(b * L_SEQ + rg1[mt]) * C_DIM + h * DH;
#pragma unroll
        for (int nt = 0; nt < 8; nt++) {
            int c = nt * 8 + 2 * tig;
            *reinterpret_cast<float2*>(y0 + c) =
                make_float2(Oa[mt][nt][0] * inv0, Oa[mt][nt][1] * inv0);
            *reinterpret_cast<float2*>(y1 + c) =
                make_float2(Oa[mt][nt][2] * inv1, Oa[mt][nt][3] * inv1);
        }
    }
}

// ---------------------------------------------------------------------------
// Launch
// ---------------------------------------------------------------------------
extern "C" void kernel_launch(void* const* d_in, const int* in_sizes, int n_in,
                              void* d_out, int out_size) {
    const float*         x    = (const float*)d_in[0];
    const unsigned char* pad  = (const unsigned char*)d_in[1];
    const float*         Wqkv = (const float*)d_in[2];
    const float*         bqkv = (const float*)d_in[3];
    const float*         Wout = (const float*)d_in[4];
    const float*         bout = (const float*)d_in[5];
    float*               out  = (float*)d_out;

    cudaFuncSetAttribute(flash_attn_kernel,
                         cudaFuncAttributeMaxDynamicSharedMemorySize, FA_SMEM);

    rope_table_kernel<<<(L_SEQ * 32 + 255) / 256, 256>>>(pad);

    dim3 g1(N_QKV / 128, M_ROWS / 128);
    qkv_gemm_kernel<<<g1, 256>>>(x, Wqkv, bqkv);

    dim3 gr(L_SEQ / 64, BH_NUM);
    rope_transpose_kernel<<<gr, 256>>>();

    dim3 ga(L_SEQ / 128, BH_NUM);
    flash_attn_kernel<<<ga, 128, FA_SMEM>>>();

    dim3 g2(C_DIM / 128, M_ROWS / 128);
    out_gemm_kernel<<<g2, 256>>>(Wout, bout, out);
}